// round 3
// baseline (speedup 1.0000x reference)
#include <cuda_runtime.h>
#include <math.h>

// Problem constants
#define T_SEQ 2048
#define HID 3584
#define NH 16
#define NKV 8
#define HD 256
#define QKV_N ((NH + 2 * NKV) * HD)   // 8192
#define ATT_N (NH * HD)               // 4096

// Scratch (static device globals — no runtime allocation)
__device__ float g_qkv[(size_t)T_SEQ * QKV_N];   // 64 MB
__device__ float g_attn[(size_t)T_SEQ * ATT_N];  // 32 MB

// ---------------------------------------------------------------------------
// SGEMM: C[M,N] = A[M,K] @ B[K,N], row-major, all dims divisible by tile dims.
// 128x128 block tile, BK=16, 256 threads, 8x8 per-thread microtile.
// ---------------------------------------------------------------------------
__global__ __launch_bounds__(256) void sgemm_kernel(
    const float* __restrict__ A, const float* __restrict__ B,
    float* __restrict__ C, int M, int N, int K)
{
    __shared__ float As[16][132];   // A^T tile, padded
    __shared__ float Bs[16][132];   // B tile, padded

    const int tid = threadIdx.x;
    const int ty = tid >> 4;        // 0..15
    const int tx = tid & 15;        // 0..15

    const float* Ab = A + (size_t)blockIdx.y * 128 * K;
    const float* Bb = B + (size_t)blockIdx.x * 128;
    float*       Cb = C + (size_t)blockIdx.y * 128 * N + (size_t)blockIdx.x * 128;

    const int arow = tid >> 2;          // 0..63
    const int acol = (tid & 3) << 2;    // 0,4,8,12
    const int brw  = tid >> 5;          // 0..7
    const int bcl  = (tid & 31) << 2;   // 0..124

    float acc[8][8];
#pragma unroll
    for (int i = 0; i < 8; i++)
#pragma unroll
        for (int j = 0; j < 8; j++) acc[i][j] = 0.0f;

    for (int k0 = 0; k0 < K; k0 += 16) {
        float4 a0 = *(const float4*)(Ab + (size_t)arow * K + k0 + acol);
        float4 a1 = *(const float4*)(Ab + (size_t)(arow + 64) * K + k0 + acol);
        float4 b0 = *(const float4*)(Bb + (size_t)(k0 + brw) * N + bcl);
        float4 b1 = *(const float4*)(Bb + (size_t)(k0 + brw + 8) * N + bcl);

        As[acol + 0][arow] = a0.x;  As[acol + 1][arow] = a0.y;
        As[acol + 2][arow] = a0.z;  As[acol + 3][arow] = a0.w;
        As[acol + 0][arow + 64] = a1.x;  As[acol + 1][arow + 64] = a1.y;
        As[acol + 2][arow + 64] = a1.z;  As[acol + 3][arow + 64] = a1.w;
        *(float4*)&Bs[brw][bcl]     = b0;
        *(float4*)&Bs[brw + 8][bcl] = b1;
        __syncthreads();

#pragma unroll
        for (int kk = 0; kk < 16; kk++) {
            float ar[8], br[8];
            *(float4*)(ar)     = *(const float4*)&As[kk][ty * 8];
            *(float4*)(ar + 4) = *(const float4*)&As[kk][ty * 8 + 4];
            *(float4*)(br)     = *(const float4*)&Bs[kk][tx * 8];
            *(float4*)(br + 4) = *(const float4*)&Bs[kk][tx * 8 + 4];
#pragma unroll
            for (int i = 0; i < 8; i++)
#pragma unroll
                for (int j = 0; j < 8; j++)
                    acc[i][j] = fmaf(ar[i], br[j], acc[i][j]);
        }
        __syncthreads();
    }

#pragma unroll
    for (int i = 0; i < 8; i++) {
        float4 v0 = make_float4(acc[i][0], acc[i][1], acc[i][2], acc[i][3]);
        float4 v1 = make_float4(acc[i][4], acc[i][5], acc[i][6], acc[i][7]);
        *(float4*)(Cb + (size_t)(ty * 8 + i) * N + tx * 8)     = v0;
        *(float4*)(Cb + (size_t)(ty * 8 + i) * N + tx * 8 + 4) = v1;
    }
}

// ---------------------------------------------------------------------------
// RoPE (neox-style) applied in place to Q heads (0..15) and K heads (16..23)
// of g_qkv. grid = (T, 24), block = 128 (one thread per rotation pair).
// ---------------------------------------------------------------------------
__global__ void rope_kernel(const int* __restrict__ positions)
{
    const int t = blockIdx.x;
    const int h = blockIdx.y;       // 0..NH+NKV-1
    const int i = threadIdx.x;      // 0..127

    float* base = g_qkv + (size_t)t * QKV_N + h * HD;
    const float pos = (float)positions[t];
    const float inv_freq = powf(10000.0f, -(float)i * (1.0f / 128.0f));
    float s, c;
    sincosf(pos * inv_freq, &s, &c);

    const float x1 = base[i];
    const float x2 = base[i + 128];
    base[i]       = x1 * c - x2 * s;
    base[i + 128] = x2 * c + x1 * s;
}

// ---------------------------------------------------------------------------
// Flash attention, 64x64 tiles, online softmax, soft-cap tanh, causal, GQA.
// One block = (q-tile, head). 256 threads as 16x16; thread (ty,tx) owns
// 4 q-rows x 16 out-cols, and computes a 4x4 S sub-tile.
// ---------------------------------------------------------------------------
#define QS_STRIDE 260
#define PS_STRIDE 65
#define ATT_SMEM_FLOATS (64 * QS_STRIDE * 2 + 64 * PS_STRIDE)

__global__ __launch_bounds__(256, 1) void attn_kernel()
{
    extern __shared__ float sm[];
    float* Qs = sm;                              // [64][QS_STRIDE]
    float* Ks = sm + 64 * QS_STRIDE;             // [64][QS_STRIDE] (reused for V)
    float* Ps = Ks + 64 * QS_STRIDE;             // [64][PS_STRIDE]

    const int tid = threadIdx.x;
    const int ty = tid >> 4;                     // 0..15
    const int tx = tid & 15;                     // 0..15
    const int qt = (int)gridDim.x - 1 - (int)blockIdx.x;  // longest blocks first
    const int h = blockIdx.y;
    const int kvh = h >> 1;                      // GQA: rep = NH/NKV = 2
    const int q0 = qt * 64;

    // Load Q tile (post-RoPE)
    {
        const float* gq = g_qkv + (size_t)q0 * QKV_N + h * HD;
        for (int it = tid; it < 64 * 64; it += 256) {
            int r = it >> 6, c4 = (it & 63) << 2;
            *(float4*)&Qs[r * QS_STRIDE + c4] =
                *(const float4*)(gq + (size_t)r * QKV_N + c4);
        }
    }

    float m[4], l[4], acc[4][16];
#pragma unroll
    for (int i = 0; i < 4; i++) {
        m[i] = -INFINITY; l[i] = 0.0f;
#pragma unroll
        for (int j = 0; j < 16; j++) acc[i][j] = 0.0f;
    }

    const float cap_mul = 0.0625f / 50.0f;   // SCALE / SOFT_CAP
    __syncthreads();

    for (int kt = 0; kt <= qt; kt++) {
        const int k0 = kt * 64;

        // ---- load K tile ----
        {
            const float* gk = g_qkv + (size_t)k0 * QKV_N + NH * HD + kvh * HD;
            for (int it = tid; it < 64 * 64; it += 256) {
                int r = it >> 6, c4 = (it & 63) << 2;
                *(float4*)&Ks[r * QS_STRIDE + c4] =
                    *(const float4*)(gk + (size_t)r * QKV_N + c4);
            }
        }
        __syncthreads();

        // ---- S = Q K^T (4x4 per thread) ----
        float s[4][4];
#pragma unroll
        for (int i = 0; i < 4; i++)
#pragma unroll
            for (int j = 0; j < 4; j++) s[i][j] = 0.0f;

#pragma unroll 4
        for (int d = 0; d < HD; d += 4) {
            float4 qv[4], kv[4];
#pragma unroll
            for (int i = 0; i < 4; i++)
                qv[i] = *(const float4*)&Qs[(ty * 4 + i) * QS_STRIDE + d];
#pragma unroll
            for (int j = 0; j < 4; j++)
                kv[j] = *(const float4*)&Ks[(tx * 4 + j) * QS_STRIDE + d];
#pragma unroll
            for (int i = 0; i < 4; i++)
#pragma unroll
                for (int j = 0; j < 4; j++) {
                    s[i][j] = fmaf(qv[i].x, kv[j].x, s[i][j]);
                    s[i][j] = fmaf(qv[i].y, kv[j].y, s[i][j]);
                    s[i][j] = fmaf(qv[i].z, kv[j].z, s[i][j]);
                    s[i][j] = fmaf(qv[i].w, kv[j].w, s[i][j]);
                }
        }

        // ---- soft-cap, causal mask, online softmax ----
        const bool diag = (kt == qt);
#pragma unroll
        for (int i = 0; i < 4; i++) {
            const int lrow = ty * 4 + i;
#pragma unroll
            for (int j = 0; j < 4; j++) {
                float z = 50.0f * tanhf(s[i][j] * cap_mul);
                if (diag && (tx * 4 + j > lrow)) z = -INFINITY;
                s[i][j] = z;
            }
        }

#pragma unroll
        for (int i = 0; i < 4; i++) {
            float rmax = fmaxf(fmaxf(s[i][0], s[i][1]), fmaxf(s[i][2], s[i][3]));
#pragma unroll
            for (int off = 8; off > 0; off >>= 1)
                rmax = fmaxf(rmax, __shfl_xor_sync(0xffffffffu, rmax, off, 16));
            const float newm = fmaxf(m[i], rmax);
            const float corr = expf(m[i] - newm);   // expf(-inf)=0 on first tile

            float psum = 0.0f;
#pragma unroll
            for (int j = 0; j < 4; j++) {
                float p = expf(s[i][j] - newm);     // -inf -> 0
                s[i][j] = p;
                psum += p;
            }
#pragma unroll
            for (int off = 8; off > 0; off >>= 1)
                psum += __shfl_xor_sync(0xffffffffu, psum, off, 16);

            l[i] = l[i] * corr + psum;
            m[i] = newm;
#pragma unroll
            for (int j = 0; j < 16; j++) acc[i][j] *= corr;
#pragma unroll
            for (int j = 0; j < 4; j++)
                Ps[(ty * 4 + i) * PS_STRIDE + tx * 4 + j] = s[i][j];
        }
        __syncthreads();   // S-compute (Ks reads) + Ps writes done

        // ---- load V tile into Ks ----
        {
            const float* gv = g_qkv + (size_t)k0 * QKV_N + (NH + NKV) * HD + kvh * HD;
            for (int it = tid; it < 64 * 64; it += 256) {
                int r = it >> 6, c4 = (it & 63) << 2;
                *(float4*)&Ks[r * QS_STRIDE + c4] =
                    *(const float4*)(gv + (size_t)r * QKV_N + c4);
            }
        }
        __syncthreads();

        // ---- acc += P @ V ----
#pragma unroll 4
        for (int j = 0; j < 64; j++) {
            float pr[4];
#pragma unroll
            for (int i = 0; i < 4; i++)
                pr[i] = Ps[(ty * 4 + i) * PS_STRIDE + j];
            const float4 v0 = *(const float4*)&Ks[j * QS_STRIDE + tx * 16];
            const float4 v1 = *(const float4*)&Ks[j * QS_STRIDE + tx * 16 + 4];
            const float4 v2 = *(const float4*)&Ks[j * QS_STRIDE + tx * 16 + 8];
            const float4 v3 = *(const float4*)&Ks[j * QS_STRIDE + tx * 16 + 12];
#pragma unroll
            for (int i = 0; i < 4; i++) {
                acc[i][0]  = fmaf(pr[i], v0.x, acc[i][0]);
                acc[i][1]  = fmaf(pr[i], v0.y, acc[i][1]);
                acc[i][2]  = fmaf(pr[i], v0.z, acc[i][2]);
                acc[i][3]  = fmaf(pr[i], v0.w, acc[i][3]);
                acc[i][4]  = fmaf(pr[i], v1.x, acc[i][4]);
                acc[i][5]  = fmaf(pr[i], v1.y, acc[i][5]);
                acc[i][6]  = fmaf(pr[i], v1.z, acc[i][6]);
                acc[i][7]  = fmaf(pr[i], v1.w, acc[i][7]);
                acc[i][8]  = fmaf(pr[i], v2.x, acc[i][8]);
                acc[i][9]  = fmaf(pr[i], v2.y, acc[i][9]);
                acc[i][10] = fmaf(pr[i], v2.z, acc[i][10]);
                acc[i][11] = fmaf(pr[i], v2.w, acc[i][11]);
                acc[i][12] = fmaf(pr[i], v3.x, acc[i][12]);
                acc[i][13] = fmaf(pr[i], v3.y, acc[i][13]);
                acc[i][14] = fmaf(pr[i], v3.z, acc[i][14]);
                acc[i][15] = fmaf(pr[i], v3.w, acc[i][15]);
            }
        }
        __syncthreads();   // before next K tile overwrites Ks
    }

    // ---- epilogue: normalize and store ----
    float* go = g_attn + (size_t)q0 * ATT_N + h * HD;
#pragma unroll
    for (int i = 0; i < 4; i++) {
        const float inv_l = 1.0f / l[i];
        const int r = ty * 4 + i;
#pragma unroll
        for (int j = 0; j < 16; j += 4) {
            float4 v = make_float4(acc[i][j] * inv_l, acc[i][j + 1] * inv_l,
                                   acc[i][j + 2] * inv_l, acc[i][j + 3] * inv_l);
            *(float4*)(go + (size_t)r * ATT_N + tx * 16 + j) = v;
        }
    }
}

// ---------------------------------------------------------------------------
// kernel_launch
// ---------------------------------------------------------------------------
extern "C" void kernel_launch(void* const* d_in, const int* in_sizes, int n_in,
                              void* d_out, int out_size)
{
    const int*   positions = (const int*)d_in[0];
    const float* hidden    = (const float*)d_in[1];
    const float* w_qkv     = (const float*)d_in[2];
    const float* w_o       = (const float*)d_in[3];
    float* out = (float*)d_out;

    float *qkv_ptr = nullptr, *attn_ptr = nullptr;
    cudaGetSymbolAddress((void**)&qkv_ptr, g_qkv);
    cudaGetSymbolAddress((void**)&attn_ptr, g_attn);

    // 1) QKV projection: [T,HID] @ [HID,QKV_N]
    {
        dim3 grid(QKV_N / 128, T_SEQ / 128);
        sgemm_kernel<<<grid, 256>>>(hidden, w_qkv, qkv_ptr, T_SEQ, QKV_N, HID);
    }

    // 2) RoPE on q + k heads
    rope_kernel<<<dim3(T_SEQ, NH + NKV), 128>>>(positions);

    // 3) Flash attention
    {
        const int smem_bytes = ATT_SMEM_FLOATS * (int)sizeof(float);  // 149760
        cudaFuncSetAttribute(attn_kernel,
                             cudaFuncAttributeMaxDynamicSharedMemorySize,
                             smem_bytes);
        attn_kernel<<<dim3(T_SEQ / 64, NH), 256, smem_bytes>>>();
    }

    // 4) Output projection: [T,ATT_N] @ [ATT_N,HID]
    {
        dim3 grid(HID / 128, T_SEQ / 128);
        sgemm_kernel<<<grid, 256>>>(attn_ptr, w_o, out, T_SEQ, HID, ATT_N);
    }
}

// round 4
// speedup vs baseline: 1.5238x; 1.5238x over previous
#include <cuda_runtime.h>
#include <cuda_bf16.h>
#include <math.h>
#include <stdint.h>

// Problem constants
#define T_SEQ 2048
#define HID 3584
#define NH 16
#define NKV 8
#define HD 256
#define QKV_N ((NH + 2 * NKV) * HD)   // 8192
#define ATT_N (NH * HD)               // 4096

// Scratch (static device globals — no runtime allocation)
__device__ float g_qkv[(size_t)T_SEQ * QKV_N];    // 64 MB
__device__ float g_attn[(size_t)T_SEQ * ATT_N];   // 32 MB

// bf16 hi/lo splits for tensor-core GEMMs
__device__ __nv_bfloat16 g_hid_hi[(size_t)T_SEQ * HID];
__device__ __nv_bfloat16 g_hid_lo[(size_t)T_SEQ * HID];
__device__ __nv_bfloat16 g_wqkv_hi[(size_t)HID * QKV_N];
__device__ __nv_bfloat16 g_wqkv_lo[(size_t)HID * QKV_N];
__device__ __nv_bfloat16 g_wo_hi[(size_t)ATT_N * HID];
__device__ __nv_bfloat16 g_wo_lo[(size_t)ATT_N * HID];
__device__ __nv_bfloat16 g_att_hi[(size_t)T_SEQ * ATT_N];
__device__ __nv_bfloat16 g_att_lo[(size_t)T_SEQ * ATT_N];

// ---------------------------------------------------------------------------
// Split fp32 -> bf16 hi + bf16 lo (residual). n must be multiple of 4.
// ---------------------------------------------------------------------------
__global__ void split_kernel(const float* __restrict__ x,
                             __nv_bfloat16* __restrict__ hi,
                             __nv_bfloat16* __restrict__ lo, size_t n)
{
    size_t i = ((size_t)blockIdx.x * blockDim.x + threadIdx.x) * 4;
    if (i >= n) return;
    float4 v = *(const float4*)(x + i);
    __nv_bfloat16 h[4], l[4];
    float vv[4] = {v.x, v.y, v.z, v.w};
#pragma unroll
    for (int j = 0; j < 4; j++) {
        h[j] = __float2bfloat16_rn(vv[j]);
        l[j] = __float2bfloat16_rn(vv[j] - __bfloat162float(h[j]));
    }
    *(uint2*)(hi + i) = *(uint2*)h;
    *(uint2*)(lo + i) = *(uint2*)l;
}

// ---------------------------------------------------------------------------
// Split-bf16 tensor-core GEMM: C[M,N](fp32) = A[M,K] @ B[K,N]
// where A ~ Ahi+Alo, B ~ Bhi+Blo (bf16). Computes hi*hi + hi*lo + lo*hi.
// 128x128 tile, BK=32, 256 threads (8 warps, 2x4), warp tile 64x32.
// mma.sync.m16n8k16.f32.bf16.bf16.f32 via ldmatrix.
// ---------------------------------------------------------------------------
__device__ __forceinline__ uint32_t smem_u32(const void* p) {
    return (uint32_t)__cvta_generic_to_shared(p);
}

__device__ __forceinline__ void ldsm_x4(uint32_t* r, uint32_t addr) {
    asm volatile("ldmatrix.sync.aligned.m8n8.x4.shared.b16 {%0,%1,%2,%3}, [%4];\n"
                 : "=r"(r[0]), "=r"(r[1]), "=r"(r[2]), "=r"(r[3]) : "r"(addr));
}
__device__ __forceinline__ void ldsm_x4_t(uint32_t* r, uint32_t addr) {
    asm volatile("ldmatrix.sync.aligned.m8n8.x4.trans.shared.b16 {%0,%1,%2,%3}, [%4];\n"
                 : "=r"(r[0]), "=r"(r[1]), "=r"(r[2]), "=r"(r[3]) : "r"(addr));
}
__device__ __forceinline__ void mma_bf16(float* c, const uint32_t* a, const uint32_t* b) {
    asm volatile(
        "mma.sync.aligned.m16n8k16.row.col.f32.bf16.bf16.f32 "
        "{%0,%1,%2,%3}, {%4,%5,%6,%7}, {%8,%9}, {%0,%1,%2,%3};\n"
        : "+f"(c[0]), "+f"(c[1]), "+f"(c[2]), "+f"(c[3])
        : "r"(a[0]), "r"(a[1]), "r"(a[2]), "r"(a[3]), "r"(b[0]), "r"(b[1]));
}

#define AS_STRIDE 40
#define BS_STRIDE 136

__global__ __launch_bounds__(256) void bgemm3_kernel(
    const __nv_bfloat16* __restrict__ Ahi_g, const __nv_bfloat16* __restrict__ Alo_g,
    const __nv_bfloat16* __restrict__ Bhi_g, const __nv_bfloat16* __restrict__ Blo_g,
    float* __restrict__ C, int M, int N, int K)
{
    __shared__ __nv_bfloat16 Ah[128][AS_STRIDE];
    __shared__ __nv_bfloat16 Al[128][AS_STRIDE];
    __shared__ __nv_bfloat16 Bh[32][BS_STRIDE];
    __shared__ __nv_bfloat16 Bl[32][BS_STRIDE];

    const int tid = threadIdx.x;
    const int wid = tid >> 5;
    const int lane = tid & 31;
    const int wm = wid & 1;        // 0..1 -> warp m origin = wm*64
    const int wn = wid >> 1;       // 0..3 -> warp n origin = wn*32

    const int bm0 = blockIdx.y * 128;
    const int bn0 = blockIdx.x * 128;

    float c[4][4][4] = {};

    for (int k0 = 0; k0 < K; k0 += 32) {
        // ---- global -> shared (fp32-free, bf16 direct) ----
#pragma unroll
        for (int c2 = 0; c2 < 2; c2++) {
            int ch = tid + c2 * 256;
            int ar = ch >> 2, ac = (ch & 3) * 8;
            *(float4*)&Ah[ar][ac] = *(const float4*)&Ahi_g[(size_t)(bm0 + ar) * K + k0 + ac];
            *(float4*)&Al[ar][ac] = *(const float4*)&Alo_g[(size_t)(bm0 + ar) * K + k0 + ac];
            int br = ch >> 4, bc = (ch & 15) * 8;
            *(float4*)&Bh[br][bc] = *(const float4*)&Bhi_g[(size_t)(k0 + br) * N + bn0 + bc];
            *(float4*)&Bl[br][bc] = *(const float4*)&Blo_g[(size_t)(k0 + br) * N + bn0 + bc];
        }
        __syncthreads();

#pragma unroll
        for (int ks = 0; ks < 32; ks += 16) {
            uint32_t ah[4][4], al[4][4], bh[4][2], bl[4][2];
            const int arow = wm * 64 + (lane & 15);
            const int acol = ks + (lane >> 4) * 8;
#pragma unroll
            for (int mi = 0; mi < 4; mi++) {
                ldsm_x4(ah[mi], smem_u32(&Ah[arow + mi * 16][acol]));
                ldsm_x4(al[mi], smem_u32(&Al[arow + mi * 16][acol]));
            }
            const int brow = ks + (lane & 15);
#pragma unroll
            for (int nj = 0; nj < 2; nj++) {
                const int bcol = wn * 32 + nj * 16 + (lane >> 4) * 8;
                uint32_t r[4];
                ldsm_x4_t(r, smem_u32(&Bh[brow][bcol]));
                bh[nj * 2][0] = r[0]; bh[nj * 2][1] = r[1];
                bh[nj * 2 + 1][0] = r[2]; bh[nj * 2 + 1][1] = r[3];
                ldsm_x4_t(r, smem_u32(&Bl[brow][bcol]));
                bl[nj * 2][0] = r[0]; bl[nj * 2][1] = r[1];
                bl[nj * 2 + 1][0] = r[2]; bl[nj * 2 + 1][1] = r[3];
            }
#pragma unroll
            for (int mi = 0; mi < 4; mi++)
#pragma unroll
                for (int ni = 0; ni < 4; ni++) {
                    mma_bf16(c[mi][ni], ah[mi], bh[ni]);   // hi*hi
                    mma_bf16(c[mi][ni], ah[mi], bl[ni]);   // hi*lo
                    mma_bf16(c[mi][ni], al[mi], bh[ni]);   // lo*hi
                }
        }
        __syncthreads();
    }

    // ---- epilogue ----
    const int gid = lane >> 2, tig = lane & 3;
#pragma unroll
    for (int mi = 0; mi < 4; mi++) {
        const int r0 = bm0 + wm * 64 + mi * 16 + gid;
#pragma unroll
        for (int ni = 0; ni < 4; ni++) {
            const int cc = bn0 + wn * 32 + ni * 8 + tig * 2;
            *(float2*)&C[(size_t)r0 * N + cc] = make_float2(c[mi][ni][0], c[mi][ni][1]);
            *(float2*)&C[(size_t)(r0 + 8) * N + cc] = make_float2(c[mi][ni][2], c[mi][ni][3]);
        }
    }
}

// ---------------------------------------------------------------------------
// RoPE (neox-style) applied in place to Q heads (0..15) and K heads (16..23)
// ---------------------------------------------------------------------------
__global__ void rope_kernel(const int* __restrict__ positions)
{
    const int t = blockIdx.x;
    const int h = blockIdx.y;
    const int i = threadIdx.x;

    float* base = g_qkv + (size_t)t * QKV_N + h * HD;
    const float pos = (float)positions[t];
    const float inv_freq = powf(10000.0f, -(float)i * (1.0f / 128.0f));
    float s, c;
    sincosf(pos * inv_freq, &s, &c);

    const float x1 = base[i];
    const float x2 = base[i + 128];
    base[i]       = x1 * c - x2 * s;
    base[i + 128] = x2 * c + x1 * s;
}

// ---------------------------------------------------------------------------
// Flash attention (fp32 FFMA, unchanged from R3)
// ---------------------------------------------------------------------------
#define QS_STRIDE 260
#define PS_STRIDE 65
#define ATT_SMEM_FLOATS (64 * QS_STRIDE * 2 + 64 * PS_STRIDE)

__global__ __launch_bounds__(256, 1) void attn_kernel()
{
    extern __shared__ float sm[];
    float* Qs = sm;
    float* Ks = sm + 64 * QS_STRIDE;
    float* Ps = Ks + 64 * QS_STRIDE;

    const int tid = threadIdx.x;
    const int ty = tid >> 4;
    const int tx = tid & 15;
    const int qt = (int)gridDim.x - 1 - (int)blockIdx.x;
    const int h = blockIdx.y;
    const int kvh = h >> 1;
    const int q0 = qt * 64;

    {
        const float* gq = g_qkv + (size_t)q0 * QKV_N + h * HD;
        for (int it = tid; it < 64 * 64; it += 256) {
            int r = it >> 6, c4 = (it & 63) << 2;
            *(float4*)&Qs[r * QS_STRIDE + c4] =
                *(const float4*)(gq + (size_t)r * QKV_N + c4);
        }
    }

    float m[4], l[4], acc[4][16];
#pragma unroll
    for (int i = 0; i < 4; i++) {
        m[i] = -INFINITY; l[i] = 0.0f;
#pragma unroll
        for (int j = 0; j < 16; j++) acc[i][j] = 0.0f;
    }

    const float cap_mul = 0.0625f / 50.0f;
    __syncthreads();

    for (int kt = 0; kt <= qt; kt++) {
        const int k0 = kt * 64;
        {
            const float* gk = g_qkv + (size_t)k0 * QKV_N + NH * HD + kvh * HD;
            for (int it = tid; it < 64 * 64; it += 256) {
                int r = it >> 6, c4 = (it & 63) << 2;
                *(float4*)&Ks[r * QS_STRIDE + c4] =
                    *(const float4*)(gk + (size_t)r * QKV_N + c4);
            }
        }
        __syncthreads();

        float s[4][4];
#pragma unroll
        for (int i = 0; i < 4; i++)
#pragma unroll
            for (int j = 0; j < 4; j++) s[i][j] = 0.0f;

#pragma unroll 4
        for (int d = 0; d < HD; d += 4) {
            float4 qv[4], kv[4];
#pragma unroll
            for (int i = 0; i < 4; i++)
                qv[i] = *(const float4*)&Qs[(ty * 4 + i) * QS_STRIDE + d];
#pragma unroll
            for (int j = 0; j < 4; j++)
                kv[j] = *(const float4*)&Ks[(tx * 4 + j) * QS_STRIDE + d];
#pragma unroll
            for (int i = 0; i < 4; i++)
#pragma unroll
                for (int j = 0; j < 4; j++) {
                    s[i][j] = fmaf(qv[i].x, kv[j].x, s[i][j]);
                    s[i][j] = fmaf(qv[i].y, kv[j].y, s[i][j]);
                    s[i][j] = fmaf(qv[i].z, kv[j].z, s[i][j]);
                    s[i][j] = fmaf(qv[i].w, kv[j].w, s[i][j]);
                }
        }

        const bool diag = (kt == qt);
#pragma unroll
        for (int i = 0; i < 4; i++) {
            const int lrow = ty * 4 + i;
#pragma unroll
            for (int j = 0; j < 4; j++) {
                float z = 50.0f * tanhf(s[i][j] * cap_mul);
                if (diag && (tx * 4 + j > lrow)) z = -INFINITY;
                s[i][j] = z;
            }
        }

#pragma unroll
        for (int i = 0; i < 4; i++) {
            float rmax = fmaxf(fmaxf(s[i][0], s[i][1]), fmaxf(s[i][2], s[i][3]));
#pragma unroll
            for (int off = 8; off > 0; off >>= 1)
                rmax = fmaxf(rmax, __shfl_xor_sync(0xffffffffu, rmax, off, 16));
            const float newm = fmaxf(m[i], rmax);
            const float corr = expf(m[i] - newm);

            float psum = 0.0f;
#pragma unroll
            for (int j = 0; j < 4; j++) {
                float p = expf(s[i][j] - newm);
                s[i][j] = p;
                psum += p;
            }
#pragma unroll
            for (int off = 8; off > 0; off >>= 1)
                psum += __shfl_xor_sync(0xffffffffu, psum, off, 16);

            l[i] = l[i] * corr + psum;
            m[i] = newm;
#pragma unroll
            for (int j = 0; j < 16; j++) acc[i][j] *= corr;
#pragma unroll
            for (int j = 0; j < 4; j++)
                Ps[(ty * 4 + i) * PS_STRIDE + tx * 4 + j] = s[i][j];
        }
        __syncthreads();

        {
            const float* gv = g_qkv + (size_t)k0 * QKV_N + (NH + NKV) * HD + kvh * HD;
            for (int it = tid; it < 64 * 64; it += 256) {
                int r = it >> 6, c4 = (it & 63) << 2;
                *(float4*)&Ks[r * QS_STRIDE + c4] =
                    *(const float4*)(gv + (size_t)r * QKV_N + c4);
            }
        }
        __syncthreads();

#pragma unroll 4
        for (int j = 0; j < 64; j++) {
            float pr[4];
#pragma unroll
            for (int i = 0; i < 4; i++)
                pr[i] = Ps[(ty * 4 + i) * PS_STRIDE + j];
            const float4 v0 = *(const float4*)&Ks[j * QS_STRIDE + tx * 16];
            const float4 v1 = *(const float4*)&Ks[j * QS_STRIDE + tx * 16 + 4];
            const float4 v2 = *(const float4*)&Ks[j * QS_STRIDE + tx * 16 + 8];
            const float4 v3 = *(const float4*)&Ks[j * QS_STRIDE + tx * 16 + 12];
#pragma unroll
            for (int i = 0; i < 4; i++) {
                acc[i][0]  = fmaf(pr[i], v0.x, acc[i][0]);
                acc[i][1]  = fmaf(pr[i], v0.y, acc[i][1]);
                acc[i][2]  = fmaf(pr[i], v0.z, acc[i][2]);
                acc[i][3]  = fmaf(pr[i], v0.w, acc[i][3]);
                acc[i][4]  = fmaf(pr[i], v1.x, acc[i][4]);
                acc[i][5]  = fmaf(pr[i], v1.y, acc[i][5]);
                acc[i][6]  = fmaf(pr[i], v1.z, acc[i][6]);
                acc[i][7]  = fmaf(pr[i], v1.w, acc[i][7]);
                acc[i][8]  = fmaf(pr[i], v2.x, acc[i][8]);
                acc[i][9]  = fmaf(pr[i], v2.y, acc[i][9]);
                acc[i][10] = fmaf(pr[i], v2.z, acc[i][10]);
                acc[i][11] = fmaf(pr[i], v2.w, acc[i][11]);
                acc[i][12] = fmaf(pr[i], v3.x, acc[i][12]);
                acc[i][13] = fmaf(pr[i], v3.y, acc[i][13]);
                acc[i][14] = fmaf(pr[i], v3.z, acc[i][14]);
                acc[i][15] = fmaf(pr[i], v3.w, acc[i][15]);
            }
        }
        __syncthreads();
    }

    float* go = g_attn + (size_t)q0 * ATT_N + h * HD;
#pragma unroll
    for (int i = 0; i < 4; i++) {
        const float inv_l = 1.0f / l[i];
        const int r = ty * 4 + i;
#pragma unroll
        for (int j = 0; j < 16; j += 4) {
            float4 v = make_float4(acc[i][j] * inv_l, acc[i][j + 1] * inv_l,
                                   acc[i][j + 2] * inv_l, acc[i][j + 3] * inv_l);
            *(float4*)(go + (size_t)r * ATT_N + tx * 16 + j) = v;
        }
    }
}

// ---------------------------------------------------------------------------
// kernel_launch
// ---------------------------------------------------------------------------
extern "C" void kernel_launch(void* const* d_in, const int* in_sizes, int n_in,
                              void* d_out, int out_size)
{
    const int*   positions = (const int*)d_in[0];
    const float* hidden    = (const float*)d_in[1];
    const float* w_qkv     = (const float*)d_in[2];
    const float* w_o       = (const float*)d_in[3];
    float* out = (float*)d_out;

    float *qkv_ptr = nullptr, *attn_ptr = nullptr;
    __nv_bfloat16 *hid_hi, *hid_lo, *wqkv_hi, *wqkv_lo, *wo_hi, *wo_lo, *att_hi, *att_lo;
    cudaGetSymbolAddress((void**)&qkv_ptr, g_qkv);
    cudaGetSymbolAddress((void**)&attn_ptr, g_attn);
    cudaGetSymbolAddress((void**)&hid_hi, g_hid_hi);
    cudaGetSymbolAddress((void**)&hid_lo, g_hid_lo);
    cudaGetSymbolAddress((void**)&wqkv_hi, g_wqkv_hi);
    cudaGetSymbolAddress((void**)&wqkv_lo, g_wqkv_lo);
    cudaGetSymbolAddress((void**)&wo_hi, g_wo_hi);
    cudaGetSymbolAddress((void**)&wo_lo, g_wo_lo);
    cudaGetSymbolAddress((void**)&att_hi, g_att_hi);
    cudaGetSymbolAddress((void**)&att_lo, g_att_lo);

    // 0) Split inputs into bf16 hi/lo
    {
        size_t n1 = (size_t)T_SEQ * HID;
        split_kernel<<<(unsigned)((n1 / 4 + 255) / 256), 256>>>(hidden, hid_hi, hid_lo, n1);
        size_t n2 = (size_t)HID * QKV_N;
        split_kernel<<<(unsigned)((n2 / 4 + 255) / 256), 256>>>(w_qkv, wqkv_hi, wqkv_lo, n2);
        size_t n3 = (size_t)ATT_N * HID;
        split_kernel<<<(unsigned)((n3 / 4 + 255) / 256), 256>>>(w_o, wo_hi, wo_lo, n3);
    }

    // 1) QKV projection: [T,HID] @ [HID,QKV_N] (tensor cores, split-bf16)
    {
        dim3 grid(QKV_N / 128, T_SEQ / 128);
        bgemm3_kernel<<<grid, 256>>>(hid_hi, hid_lo, wqkv_hi, wqkv_lo,
                                     qkv_ptr, T_SEQ, QKV_N, HID);
    }

    // 2) RoPE on q + k heads
    rope_kernel<<<dim3(T_SEQ, NH + NKV), 128>>>(positions);

    // 3) Flash attention
    {
        const int smem_bytes = ATT_SMEM_FLOATS * (int)sizeof(float);
        cudaFuncSetAttribute(attn_kernel,
                             cudaFuncAttributeMaxDynamicSharedMemorySize,
                             smem_bytes);
        attn_kernel<<<dim3(T_SEQ / 64, NH), 256, smem_bytes>>>();
    }

    // 4) Split attention output, then O projection (tensor cores)
    {
        size_t n4 = (size_t)T_SEQ * ATT_N;
        split_kernel<<<(unsigned)((n4 / 4 + 255) / 256), 256>>>(attn_ptr, att_hi, att_lo, n4);
        dim3 grid(HID / 128, T_SEQ / 128);
        bgemm3_kernel<<<grid, 256>>>(att_hi, att_lo, wo_hi, wo_lo,
                                     out, T_SEQ, HID, ATT_N);
    }
}

// round 6
// speedup vs baseline: 2.1094x; 1.3843x over previous
#include <cuda_runtime.h>
#include <cuda_bf16.h>
#include <math.h>
#include <stdint.h>

// Problem constants
#define T_SEQ 2048
#define HID 3584
#define NH 16
#define NKV 8
#define HD 256
#define QKV_N ((NH + 2 * NKV) * HD)   // 8192
#define ATT_N (NH * HD)               // 4096

// Scratch (static device globals — no runtime allocation)
__device__ float g_qkv[(size_t)T_SEQ * QKV_N];    // 64 MB

// bf16 hi/lo splits for tensor-core GEMMs
__device__ __nv_bfloat16 g_hid_hi[(size_t)T_SEQ * HID];
__device__ __nv_bfloat16 g_hid_lo[(size_t)T_SEQ * HID];
__device__ __nv_bfloat16 g_wqkv_hi[(size_t)HID * QKV_N];
__device__ __nv_bfloat16 g_wqkv_lo[(size_t)HID * QKV_N];
__device__ __nv_bfloat16 g_wo_hi[(size_t)ATT_N * HID];
__device__ __nv_bfloat16 g_wo_lo[(size_t)ATT_N * HID];
__device__ __nv_bfloat16 g_att_hi[(size_t)T_SEQ * ATT_N];
__device__ __nv_bfloat16 g_att_lo[(size_t)T_SEQ * ATT_N];

// head-major post-RoPE Q/K/V splits for attention: [head][t][d]
__device__ __nv_bfloat16 g_q_hi[(size_t)NH * T_SEQ * HD];
__device__ __nv_bfloat16 g_q_lo[(size_t)NH * T_SEQ * HD];
__device__ __nv_bfloat16 g_k_hi[(size_t)NKV * T_SEQ * HD];
__device__ __nv_bfloat16 g_k_lo[(size_t)NKV * T_SEQ * HD];
__device__ __nv_bfloat16 g_v_hi[(size_t)NKV * T_SEQ * HD];
__device__ __nv_bfloat16 g_v_lo[(size_t)NKV * T_SEQ * HD];

// ---------------------------------------------------------------------------
// helpers
// ---------------------------------------------------------------------------
__device__ __forceinline__ uint32_t smem_u32(const void* p) {
    return (uint32_t)__cvta_generic_to_shared(p);
}
__device__ __forceinline__ void ldsm_x4(uint32_t* r, uint32_t addr) {
    asm volatile("ldmatrix.sync.aligned.m8n8.x4.shared.b16 {%0,%1,%2,%3}, [%4];\n"
                 : "=r"(r[0]), "=r"(r[1]), "=r"(r[2]), "=r"(r[3]) : "r"(addr));
}
__device__ __forceinline__ void ldsm_x4_t(uint32_t* r, uint32_t addr) {
    asm volatile("ldmatrix.sync.aligned.m8n8.x4.trans.shared.b16 {%0,%1,%2,%3}, [%4];\n"
                 : "=r"(r[0]), "=r"(r[1]), "=r"(r[2]), "=r"(r[3]) : "r"(addr));
}
__device__ __forceinline__ void mma_bf16(float* c, const uint32_t* a, const uint32_t* b) {
    asm volatile(
        "mma.sync.aligned.m16n8k16.row.col.f32.bf16.bf16.f32 "
        "{%0,%1,%2,%3}, {%4,%5,%6,%7}, {%8,%9}, {%0,%1,%2,%3};\n"
        : "+f"(c[0]), "+f"(c[1]), "+f"(c[2]), "+f"(c[3])
        : "r"(a[0]), "r"(a[1]), "r"(a[2]), "r"(a[3]), "r"(b[0]), "r"(b[1]));
}
__device__ __forceinline__ void split2(float x, __nv_bfloat16& h, __nv_bfloat16& l) {
    h = __float2bfloat16_rn(x);
    l = __float2bfloat16_rn(x - __bfloat162float(h));
}
__device__ __forceinline__ uint32_t pack_bf2(__nv_bfloat16 a, __nv_bfloat16 b) {
    __nv_bfloat162 t;
    t.x = a; t.y = b;           // x = low half
    uint32_t r;
    memcpy(&r, &t, 4);
    return r;
}

// ---------------------------------------------------------------------------
// Split fp32 -> bf16 hi + bf16 lo (residual). n must be multiple of 4.
// ---------------------------------------------------------------------------
__global__ void split_kernel(const float* __restrict__ x,
                             __nv_bfloat16* __restrict__ hi,
                             __nv_bfloat16* __restrict__ lo, size_t n)
{
    size_t i = ((size_t)blockIdx.x * blockDim.x + threadIdx.x) * 4;
    if (i >= n) return;
    float4 v = *(const float4*)(x + i);
    __nv_bfloat16 h[4], l[4];
    float vv[4] = {v.x, v.y, v.z, v.w};
#pragma unroll
    for (int j = 0; j < 4; j++) split2(vv[j], h[j], l[j]);
    *(uint2*)(hi + i) = *(uint2*)h;
    *(uint2*)(lo + i) = *(uint2*)l;
}

// ---------------------------------------------------------------------------
// Split-bf16 tensor-core GEMM (validated in R4): C = A@B with A~Ahi+Alo etc.
// ---------------------------------------------------------------------------
#define AS_STRIDE 40
#define BS_STRIDE 136

__global__ __launch_bounds__(256) void bgemm3_kernel(
    const __nv_bfloat16* __restrict__ Ahi_g, const __nv_bfloat16* __restrict__ Alo_g,
    const __nv_bfloat16* __restrict__ Bhi_g, const __nv_bfloat16* __restrict__ Blo_g,
    float* __restrict__ C, int M, int N, int K)
{
    __shared__ __nv_bfloat16 Ah[128][AS_STRIDE];
    __shared__ __nv_bfloat16 Al[128][AS_STRIDE];
    __shared__ __nv_bfloat16 Bh[32][BS_STRIDE];
    __shared__ __nv_bfloat16 Bl[32][BS_STRIDE];

    const int tid = threadIdx.x;
    const int wid = tid >> 5;
    const int lane = tid & 31;
    const int wm = wid & 1;
    const int wn = wid >> 1;

    const int bm0 = blockIdx.y * 128;
    const int bn0 = blockIdx.x * 128;

    float c[4][4][4] = {};

    for (int k0 = 0; k0 < K; k0 += 32) {
#pragma unroll
        for (int c2 = 0; c2 < 2; c2++) {
            int ch = tid + c2 * 256;
            int ar = ch >> 2, ac = (ch & 3) * 8;
            *(float4*)&Ah[ar][ac] = *(const float4*)&Ahi_g[(size_t)(bm0 + ar) * K + k0 + ac];
            *(float4*)&Al[ar][ac] = *(const float4*)&Alo_g[(size_t)(bm0 + ar) * K + k0 + ac];
            int br = ch >> 4, bc = (ch & 15) * 8;
            *(float4*)&Bh[br][bc] = *(const float4*)&Bhi_g[(size_t)(k0 + br) * N + bn0 + bc];
            *(float4*)&Bl[br][bc] = *(const float4*)&Blo_g[(size_t)(k0 + br) * N + bn0 + bc];
        }
        __syncthreads();

#pragma unroll
        for (int ks = 0; ks < 32; ks += 16) {
            uint32_t ah[4][4], al[4][4], bh[4][2], bl[4][2];
            const int arow = wm * 64 + (lane & 15);
            const int acol = ks + (lane >> 4) * 8;
#pragma unroll
            for (int mi = 0; mi < 4; mi++) {
                ldsm_x4(ah[mi], smem_u32(&Ah[arow + mi * 16][acol]));
                ldsm_x4(al[mi], smem_u32(&Al[arow + mi * 16][acol]));
            }
            const int brow = ks + (lane & 15);
#pragma unroll
            for (int nj = 0; nj < 2; nj++) {
                const int bcol = wn * 32 + nj * 16 + (lane >> 4) * 8;
                uint32_t r[4];
                ldsm_x4_t(r, smem_u32(&Bh[brow][bcol]));
                bh[nj * 2][0] = r[0]; bh[nj * 2][1] = r[1];
                bh[nj * 2 + 1][0] = r[2]; bh[nj * 2 + 1][1] = r[3];
                ldsm_x4_t(r, smem_u32(&Bl[brow][bcol]));
                bl[nj * 2][0] = r[0]; bl[nj * 2][1] = r[1];
                bl[nj * 2 + 1][0] = r[2]; bl[nj * 2 + 1][1] = r[3];
            }
#pragma unroll
            for (int mi = 0; mi < 4; mi++)
#pragma unroll
                for (int ni = 0; ni < 4; ni++) {
                    mma_bf16(c[mi][ni], ah[mi], bh[ni]);
                    mma_bf16(c[mi][ni], ah[mi], bl[ni]);
                    mma_bf16(c[mi][ni], al[mi], bh[ni]);
                }
        }
        __syncthreads();
    }

    const int gid = lane >> 2, tig = lane & 3;
#pragma unroll
    for (int mi = 0; mi < 4; mi++) {
        const int r0 = bm0 + wm * 64 + mi * 16 + gid;
#pragma unroll
        for (int ni = 0; ni < 4; ni++) {
            const int cc = bn0 + wn * 32 + ni * 8 + tig * 2;
            *(float2*)&C[(size_t)r0 * N + cc] = make_float2(c[mi][ni][0], c[mi][ni][1]);
            *(float2*)&C[(size_t)(r0 + 8) * N + cc] = make_float2(c[mi][ni][2], c[mi][ni][3]);
        }
    }
}

// ---------------------------------------------------------------------------
// RoPE + split: read fp32 qkv, apply neox RoPE to q/k (v passthrough),
// write bf16 hi/lo head-major arrays [head][t][d].
// grid = (T, NH + 2*NKV), block = 128 (thread i handles dims i and i+128).
// ---------------------------------------------------------------------------
__global__ void rope_split_kernel(const int* __restrict__ positions)
{
    const int t = blockIdx.x;
    const int hh = blockIdx.y;     // 0..31
    const int i = threadIdx.x;     // 0..127

    float y1, y2;
    __nv_bfloat16 *dst_hi, *dst_lo;

    if (hh < NH + NKV) {
        // q head (hh<NH) or k head
        const int head_off = (hh < NH) ? hh : (NH + (hh - NH));
        const float* src = g_qkv + (size_t)t * QKV_N + head_off * HD;
        const float pos = (float)positions[t];
        const float inv_freq = powf(10000.0f, -(float)i * (1.0f / 128.0f));
        float s, c;
        sincosf(pos * inv_freq, &s, &c);
        const float x1 = src[i];
        const float x2 = src[i + 128];
        y1 = x1 * c - x2 * s;
        y2 = x2 * c + x1 * s;
        if (hh < NH) {
            dst_hi = g_q_hi + ((size_t)hh * T_SEQ + t) * HD;
            dst_lo = g_q_lo + ((size_t)hh * T_SEQ + t) * HD;
        } else {
            const int kvh = hh - NH;
            dst_hi = g_k_hi + ((size_t)kvh * T_SEQ + t) * HD;
            dst_lo = g_k_lo + ((size_t)kvh * T_SEQ + t) * HD;
        }
    } else {
        const int vh = hh - (NH + NKV);
        const float* src = g_qkv + (size_t)t * QKV_N + (NH + NKV + vh) * HD;
        y1 = src[i];
        y2 = src[i + 128];
        dst_hi = g_v_hi + ((size_t)vh * T_SEQ + t) * HD;
        dst_lo = g_v_lo + ((size_t)vh * T_SEQ + t) * HD;
    }

    __nv_bfloat16 h1, l1, h2, l2;
    split2(y1, h1, l1);
    split2(y2, h2, l2);
    dst_hi[i] = h1;        dst_lo[i] = l1;
    dst_hi[i + 128] = h2;  dst_lo[i + 128] = l2;
}

// ---------------------------------------------------------------------------
// Tensor-core flash attention (split-bf16).
// Block = (q-tile of 64, head). 128 threads = 4 warps; warp w owns q-rows
// [w*16, w*16+16). S via 3-MMA split QK^T; P split in regs; PV via 3-MMA.
// Writes att_hi/att_lo bf16 directly (fused pre-O-proj split).
// ---------------------------------------------------------------------------
#define ATS 264                         // smem row stride (bf16 elems), 256+8
#define ATILE (64 * ATS)                // elems per 64x256 tile
#define ATT2_SMEM_BYTES (6 * ATILE * 2) // 202752

__global__ __launch_bounds__(128, 1) void attn_mma_kernel()
{
    extern __shared__ __nv_bfloat16 sb[];
    __nv_bfloat16* SQh = sb;
    __nv_bfloat16* SQl = sb + ATILE;
    __nv_bfloat16* SKh = sb + 2 * ATILE;
    __nv_bfloat16* SKl = sb + 3 * ATILE;
    __nv_bfloat16* SVh = sb + 4 * ATILE;
    __nv_bfloat16* SVl = sb + 5 * ATILE;

    const int tid = threadIdx.x;
    const int lane = tid & 31;
    const int warp = tid >> 5;
    const int qt = (int)gridDim.x - 1 - (int)blockIdx.x;
    const int h = blockIdx.y;
    const int kvh = h >> 1;
    const int q0 = qt * 64;

    // ---- load Q tile ----
    {
        const __nv_bfloat16* gqh = g_q_hi + ((size_t)h * T_SEQ + q0) * HD;
        const __nv_bfloat16* gql = g_q_lo + ((size_t)h * T_SEQ + q0) * HD;
        for (int it = tid; it < 64 * 32; it += 128) {
            int r = it >> 5, c = (it & 31) * 8;
            *(float4*)&SQh[r * ATS + c] = *(const float4*)(gqh + (size_t)r * HD + c);
            *(float4*)&SQl[r * ATS + c] = *(const float4*)(gql + (size_t)r * HD + c);
        }
    }

    float acc[32][4];
#pragma unroll
    for (int n = 0; n < 32; n++)
#pragma unroll
        for (int e = 0; e < 4; e++) acc[n][e] = 0.0f;
    float m0 = -INFINITY, m1 = -INFINITY, l0 = 0.0f, l1 = 0.0f;

    const float cap_mul = 0.0625f / 50.0f;   // SCALE / SOFT_CAP

    // ldsm address components
    const int qrow = warp * 16 + (lane & 15);
    const int qc8 = (lane >> 4) << 3;
    const int krow_b = ((lane >> 4) << 3) + (lane & 7);
    const int kc8 = ((lane >> 3) & 1) << 3;
    const int vrow_b = lane & 15;
    const int vc8 = (lane >> 4) << 3;

    const __nv_bfloat16* gkh = g_k_hi + (size_t)kvh * T_SEQ * HD;
    const __nv_bfloat16* gkl = g_k_lo + (size_t)kvh * T_SEQ * HD;
    const __nv_bfloat16* gvh = g_v_hi + (size_t)kvh * T_SEQ * HD;
    const __nv_bfloat16* gvl = g_v_lo + (size_t)kvh * T_SEQ * HD;

    for (int kt = 0; kt <= qt; kt++) {
        const int k0 = kt * 64;
        __syncthreads();   // previous PV reads done before overwriting K/V
        for (int it = tid; it < 64 * 32; it += 128) {
            int r = it >> 5, c = (it & 31) * 8;
            size_t g = (size_t)(k0 + r) * HD + c;
            *(float4*)&SKh[r * ATS + c] = *(const float4*)(gkh + g);
            *(float4*)&SKl[r * ATS + c] = *(const float4*)(gkl + g);
            *(float4*)&SVh[r * ATS + c] = *(const float4*)(gvh + g);
            *(float4*)&SVl[r * ATS + c] = *(const float4*)(gvl + g);
        }
        __syncthreads();

        // ---- S = Q K^T, split 3-MMA ----
        float sc[8][4];
#pragma unroll
        for (int n = 0; n < 8; n++)
#pragma unroll
            for (int e = 0; e < 4; e++) sc[n][e] = 0.0f;

#pragma unroll 2
        for (int ks = 0; ks < HD; ks += 16) {
            uint32_t aqh[4], aql[4];
            ldsm_x4(aqh, smem_u32(&SQh[qrow * ATS + ks + qc8]));
            ldsm_x4(aql, smem_u32(&SQl[qrow * ATS + ks + qc8]));
#pragma unroll
            for (int p4 = 0; p4 < 4; p4++) {
                uint32_t bh[4], bl[4];
                const int kr = p4 * 16 + krow_b;
                ldsm_x4(bh, smem_u32(&SKh[kr * ATS + ks + kc8]));
                ldsm_x4(bl, smem_u32(&SKl[kr * ATS + ks + kc8]));
                mma_bf16(sc[2 * p4], aqh, bh);
                mma_bf16(sc[2 * p4], aqh, bl);
                mma_bf16(sc[2 * p4], aql, bh);
                mma_bf16(sc[2 * p4 + 1], aqh, bh + 2);
                mma_bf16(sc[2 * p4 + 1], aqh, bl + 2);
                mma_bf16(sc[2 * p4 + 1], aql, bh + 2);
            }
        }

        // ---- soft-cap + causal mask ----
        const bool diag = (kt == qt);
        const int colb = k0 + 2 * (lane & 3);
        const int rowg = q0 + warp * 16 + (lane >> 2);
#pragma unroll
        for (int nt = 0; nt < 8; nt++) {
#pragma unroll
            for (int e = 0; e < 4; e++) {
                float z = 50.0f * tanhf(sc[nt][e] * cap_mul);
                if (diag) {
                    int col = colb + nt * 8 + (e & 1);
                    int row = rowg + ((e >> 1) << 3);
                    if (col > row) z = -INFINITY;
                }
                sc[nt][e] = z;
            }
        }

        // ---- online softmax (rows g and g+8) ----
        float rm0 = -INFINITY, rm1 = -INFINITY;
#pragma unroll
        for (int nt = 0; nt < 8; nt++) {
            rm0 = fmaxf(rm0, fmaxf(sc[nt][0], sc[nt][1]));
            rm1 = fmaxf(rm1, fmaxf(sc[nt][2], sc[nt][3]));
        }
        rm0 = fmaxf(rm0, __shfl_xor_sync(0xffffffffu, rm0, 1));
        rm0 = fmaxf(rm0, __shfl_xor_sync(0xffffffffu, rm0, 2));
        rm1 = fmaxf(rm1, __shfl_xor_sync(0xffffffffu, rm1, 1));
        rm1 = fmaxf(rm1, __shfl_xor_sync(0xffffffffu, rm1, 2));

        const float nm0 = fmaxf(m0, rm0);
        const float nm1 = fmaxf(m1, rm1);
        const float cr0 = __expf(m0 - nm0);
        const float cr1 = __expf(m1 - nm1);

        float ps0 = 0.0f, ps1 = 0.0f;
#pragma unroll
        for (int nt = 0; nt < 8; nt++) {
            float p0 = __expf(sc[nt][0] - nm0);
            float p1 = __expf(sc[nt][1] - nm0);
            float p2 = __expf(sc[nt][2] - nm1);
            float p3 = __expf(sc[nt][3] - nm1);
            sc[nt][0] = p0; sc[nt][1] = p1; sc[nt][2] = p2; sc[nt][3] = p3;
            ps0 += p0 + p1;
            ps1 += p2 + p3;
        }
        ps0 += __shfl_xor_sync(0xffffffffu, ps0, 1);
        ps0 += __shfl_xor_sync(0xffffffffu, ps0, 2);
        ps1 += __shfl_xor_sync(0xffffffffu, ps1, 1);
        ps1 += __shfl_xor_sync(0xffffffffu, ps1, 2);

        l0 = l0 * cr0 + ps0;
        l1 = l1 * cr1 + ps1;
        m0 = nm0; m1 = nm1;

#pragma unroll
        for (int n = 0; n < 32; n++) {
            acc[n][0] *= cr0; acc[n][1] *= cr0;
            acc[n][2] *= cr1; acc[n][3] *= cr1;
        }

        // ---- convert P to split-bf16 A-fragments ----
        uint32_t ph[4][4], pl[4][4];
#pragma unroll
        for (int j = 0; j < 4; j++) {
            __nv_bfloat16 h0, lo0, h1, lo1;
#pragma unroll
            for (int half = 0; half < 2; half++) {
                const int nt = 2 * j + half;
                split2(sc[nt][0], h0, lo0);
                split2(sc[nt][1], h1, lo1);
                ph[j][2 * half] = pack_bf2(h0, h1);
                pl[j][2 * half] = pack_bf2(lo0, lo1);
                split2(sc[nt][2], h0, lo0);
                split2(sc[nt][3], h1, lo1);
                ph[j][2 * half + 1] = pack_bf2(h0, h1);
                pl[j][2 * half + 1] = pack_bf2(lo0, lo1);
            }
        }

        // ---- acc += P V, split 3-MMA ----
#pragma unroll
        for (int kk = 0; kk < 4; kk++) {
            const int vr = kk * 16 + vrow_b;
#pragma unroll
            for (int np = 0; np < 16; np++) {
                uint32_t bvh[4], bvl[4];
                const int vc = np * 16 + vc8;
                ldsm_x4_t(bvh, smem_u32(&SVh[vr * ATS + vc]));
                ldsm_x4_t(bvl, smem_u32(&SVl[vr * ATS + vc]));
                mma_bf16(acc[2 * np], ph[kk], bvh);
                mma_bf16(acc[2 * np], ph[kk], bvl);
                mma_bf16(acc[2 * np], pl[kk], bvh);
                mma_bf16(acc[2 * np + 1], ph[kk], bvh + 2);
                mma_bf16(acc[2 * np + 1], ph[kk], bvl + 2);
                mma_bf16(acc[2 * np + 1], pl[kk], bvh + 2);
            }
        }
    }

    // ---- epilogue: normalize, split to bf16 hi/lo, store ----
    const float il0 = 1.0f / l0;
    const float il1 = 1.0f / l1;
    const size_t rowA = (size_t)(q0 + warp * 16 + (lane >> 2));
    const size_t rowB = rowA + 8;
    const int cb = h * HD + 2 * (lane & 3);
#pragma unroll
    for (int nt = 0; nt < 32; nt++) {
        const int c = cb + nt * 8;
        float o0 = acc[nt][0] * il0, o1 = acc[nt][1] * il0;
        float o2 = acc[nt][2] * il1, o3 = acc[nt][3] * il1;
        __nv_bfloat16 h0, lo0, h1, lo1;
        split2(o0, h0, lo0); split2(o1, h1, lo1);
        *(uint32_t*)&g_att_hi[rowA * ATT_N + c] = pack_bf2(h0, h1);
        *(uint32_t*)&g_att_lo[rowA * ATT_N + c] = pack_bf2(lo0, lo1);
        split2(o2, h0, lo0); split2(o3, h1, lo1);
        *(uint32_t*)&g_att_hi[rowB * ATT_N + c] = pack_bf2(h0, h1);
        *(uint32_t*)&g_att_lo[rowB * ATT_N + c] = pack_bf2(lo0, lo1);
    }
}

// ---------------------------------------------------------------------------
// kernel_launch
// ---------------------------------------------------------------------------
extern "C" void kernel_launch(void* const* d_in, const int* in_sizes, int n_in,
                              void* d_out, int out_size)
{
    const int*   positions = (const int*)d_in[0];
    const float* hidden    = (const float*)d_in[1];
    const float* w_qkv     = (const float*)d_in[2];
    const float* w_o       = (const float*)d_in[3];
    float* out = (float*)d_out;

    float* qkv_ptr = nullptr;
    __nv_bfloat16 *hid_hi, *hid_lo, *wqkv_hi, *wqkv_lo, *wo_hi, *wo_lo, *att_hi, *att_lo;
    cudaGetSymbolAddress((void**)&qkv_ptr, g_qkv);
    cudaGetSymbolAddress((void**)&hid_hi, g_hid_hi);
    cudaGetSymbolAddress((void**)&hid_lo, g_hid_lo);
    cudaGetSymbolAddress((void**)&wqkv_hi, g_wqkv_hi);
    cudaGetSymbolAddress((void**)&wqkv_lo, g_wqkv_lo);
    cudaGetSymbolAddress((void**)&wo_hi, g_wo_hi);
    cudaGetSymbolAddress((void**)&wo_lo, g_wo_lo);
    cudaGetSymbolAddress((void**)&att_hi, g_att_hi);
    cudaGetSymbolAddress((void**)&att_lo, g_att_lo);

    // 0) Split inputs into bf16 hi/lo
    {
        size_t n1 = (size_t)T_SEQ * HID;
        split_kernel<<<(unsigned)((n1 / 4 + 255) / 256), 256>>>(hidden, hid_hi, hid_lo, n1);
        size_t n2 = (size_t)HID * QKV_N;
        split_kernel<<<(unsigned)((n2 / 4 + 255) / 256), 256>>>(w_qkv, wqkv_hi, wqkv_lo, n2);
        size_t n3 = (size_t)ATT_N * HID;
        split_kernel<<<(unsigned)((n3 / 4 + 255) / 256), 256>>>(w_o, wo_hi, wo_lo, n3);
    }

    // 1) QKV projection (tensor cores, split-bf16)
    {
        dim3 grid(QKV_N / 128, T_SEQ / 128);
        bgemm3_kernel<<<grid, 256>>>(hid_hi, hid_lo, wqkv_hi, wqkv_lo,
                                     qkv_ptr, T_SEQ, QKV_N, HID);
    }

    // 2) RoPE + split to head-major bf16 hi/lo Q/K/V
    rope_split_kernel<<<dim3(T_SEQ, NH + 2 * NKV), 128>>>(positions);

    // 3) Tensor-core flash attention -> att_hi/att_lo
    {
        cudaFuncSetAttribute(attn_mma_kernel,
                             cudaFuncAttributeMaxDynamicSharedMemorySize,
                             ATT2_SMEM_BYTES);
        attn_mma_kernel<<<dim3(T_SEQ / 64, NH), 128, ATT2_SMEM_BYTES>>>();
    }

    // 4) O projection (tensor cores, split-bf16)
    {
        dim3 grid(HID / 128, T_SEQ / 128);
        bgemm3_kernel<<<grid, 256>>>(att_hi, att_lo, wo_hi, wo_lo,
                                     out, T_SEQ, HID, ATT_N);
    }
}

// round 8
// speedup vs baseline: 3.4924x; 1.6557x over previous
#include <cuda_runtime.h>
#include <cuda_bf16.h>
#include <math.h>
#include <stdint.h>

// Problem constants
#define T_SEQ 2048
#define HID 3584
#define NH 16
#define NKV 8
#define HD 256
#define QKV_N ((NH + 2 * NKV) * HD)   // 8192
#define ATT_N (NH * HD)               // 4096

// Scratch (static device globals — no runtime allocation)
__device__ float g_qkv[(size_t)T_SEQ * QKV_N];    // 64 MB

// bf16 hi/lo splits for tensor-core GEMMs
__device__ __nv_bfloat16 g_hid_hi[(size_t)T_SEQ * HID];
__device__ __nv_bfloat16 g_hid_lo[(size_t)T_SEQ * HID];
__device__ __nv_bfloat16 g_wqkv_hi[(size_t)HID * QKV_N];
__device__ __nv_bfloat16 g_wqkv_lo[(size_t)HID * QKV_N];
__device__ __nv_bfloat16 g_wo_hi[(size_t)ATT_N * HID];
__device__ __nv_bfloat16 g_wo_lo[(size_t)ATT_N * HID];
__device__ __nv_bfloat16 g_att_hi[(size_t)T_SEQ * ATT_N];
__device__ __nv_bfloat16 g_att_lo[(size_t)T_SEQ * ATT_N];

// head-major post-RoPE Q/K/V splits for attention: [head][t][d]
__device__ __nv_bfloat16 g_q_hi[(size_t)NH * T_SEQ * HD];
__device__ __nv_bfloat16 g_q_lo[(size_t)NH * T_SEQ * HD];
__device__ __nv_bfloat16 g_k_hi[(size_t)NKV * T_SEQ * HD];
__device__ __nv_bfloat16 g_k_lo[(size_t)NKV * T_SEQ * HD];
__device__ __nv_bfloat16 g_v_hi[(size_t)NKV * T_SEQ * HD];
__device__ __nv_bfloat16 g_v_lo[(size_t)NKV * T_SEQ * HD];

// ---------------------------------------------------------------------------
// helpers
// ---------------------------------------------------------------------------
__device__ __forceinline__ uint32_t smem_u32(const void* p) {
    return (uint32_t)__cvta_generic_to_shared(p);
}
__device__ __forceinline__ void ldsm_x4(uint32_t* r, uint32_t addr) {
    asm volatile("ldmatrix.sync.aligned.m8n8.x4.shared.b16 {%0,%1,%2,%3}, [%4];\n"
                 : "=r"(r[0]), "=r"(r[1]), "=r"(r[2]), "=r"(r[3]) : "r"(addr));
}
__device__ __forceinline__ void ldsm_x4_t(uint32_t* r, uint32_t addr) {
    asm volatile("ldmatrix.sync.aligned.m8n8.x4.trans.shared.b16 {%0,%1,%2,%3}, [%4];\n"
                 : "=r"(r[0]), "=r"(r[1]), "=r"(r[2]), "=r"(r[3]) : "r"(addr));
}
__device__ __forceinline__ void mma_bf16(float* c, const uint32_t* a, const uint32_t* b) {
    asm volatile(
        "mma.sync.aligned.m16n8k16.row.col.f32.bf16.bf16.f32 "
        "{%0,%1,%2,%3}, {%4,%5,%6,%7}, {%8,%9}, {%0,%1,%2,%3};\n"
        : "+f"(c[0]), "+f"(c[1]), "+f"(c[2]), "+f"(c[3])
        : "r"(a[0]), "r"(a[1]), "r"(a[2]), "r"(a[3]), "r"(b[0]), "r"(b[1]));
}
__device__ __forceinline__ void cp_async16(uint32_t smem_addr, const void* gptr) {
    asm volatile("cp.async.cg.shared.global [%0], [%1], 16;\n"
                 :: "r"(smem_addr), "l"(gptr));
}
__device__ __forceinline__ void cp_commit() {
    asm volatile("cp.async.commit_group;\n");
}
template <int N>
__device__ __forceinline__ void cp_wait() {
    asm volatile("cp.async.wait_group %0;\n" :: "n"(N));
}
__device__ __forceinline__ void split2(float x, __nv_bfloat16& h, __nv_bfloat16& l) {
    h = __float2bfloat16_rn(x);
    l = __float2bfloat16_rn(x - __bfloat162float(h));
}
__device__ __forceinline__ uint32_t pack_bf2(__nv_bfloat16 a, __nv_bfloat16 b) {
    __nv_bfloat162 t;
    t.x = a; t.y = b;
    uint32_t r;
    memcpy(&r, &t, 4);
    return r;
}

// ---------------------------------------------------------------------------
// Split fp32 -> bf16 hi + bf16 lo (residual). n must be multiple of 4.
// ---------------------------------------------------------------------------
__global__ void split_kernel(const float* __restrict__ x,
                             __nv_bfloat16* __restrict__ hi,
                             __nv_bfloat16* __restrict__ lo, size_t n)
{
    size_t i = ((size_t)blockIdx.x * blockDim.x + threadIdx.x) * 4;
    if (i >= n) return;
    float4 v = *(const float4*)(x + i);
    __nv_bfloat16 h[4], l[4];
    float vv[4] = {v.x, v.y, v.z, v.w};
#pragma unroll
    for (int j = 0; j < 4; j++) split2(vv[j], h[j], l[j]);
    *(uint2*)(hi + i) = *(uint2*)h;
    *(uint2*)(lo + i) = *(uint2*)l;
}

// ---------------------------------------------------------------------------
// Split-bf16 tensor-core GEMM with 2-stage cp.async pipeline.
// C[M,N](fp32) = A@B, A~Ahi+Alo, B~Bhi+Blo. 128x128 tile, BK=32, 256 thr.
// ---------------------------------------------------------------------------
#define AS_STRIDE 40
#define BS_STRIDE 136
// per-stage element counts (bf16)
#define G_AH 0
#define G_AL (128 * AS_STRIDE)
#define G_BH (2 * 128 * AS_STRIDE)
#define G_BL (2 * 128 * AS_STRIDE + 32 * BS_STRIDE)
#define G_STAGE (2 * 128 * AS_STRIDE + 2 * 32 * BS_STRIDE)   // 18944 elems
#define GEMM_SMEM_BYTES (2 * G_STAGE * 2)                    // 75776 B

__global__ __launch_bounds__(256) void bgemm3_kernel(
    const __nv_bfloat16* __restrict__ Ahi_g, const __nv_bfloat16* __restrict__ Alo_g,
    const __nv_bfloat16* __restrict__ Bhi_g, const __nv_bfloat16* __restrict__ Blo_g,
    float* __restrict__ C, int M, int N, int K)
{
    extern __shared__ __nv_bfloat16 gs[];

    const int tid = threadIdx.x;
    const int wid = tid >> 5;
    const int lane = tid & 31;
    const int wm = wid & 1;
    const int wn = wid >> 1;

    const int bm0 = blockIdx.y * 128;
    const int bn0 = blockIdx.x * 128;

    // per-thread load coordinates (2 chunks of each array)
    const int ch0 = tid, ch1 = tid + 256;
    const int ar0 = ch0 >> 2, ac0 = (ch0 & 3) * 8;
    const int ar1 = ch1 >> 2, ac1 = (ch1 & 3) * 8;
    const int br0 = ch0 >> 4, bc0 = (ch0 & 15) * 8;
    const int br1 = ch1 >> 4, bc1 = (ch1 & 15) * 8;

    const int NIT = K / 32;

    auto issue_stage = [&](int stage, int k0) {
        __nv_bfloat16* S = gs + stage * G_STAGE;
        uint32_t sAh = smem_u32(S + G_AH);
        uint32_t sAl = smem_u32(S + G_AL);
        uint32_t sBh = smem_u32(S + G_BH);
        uint32_t sBl = smem_u32(S + G_BL);
        cp_async16(sAh + (ar0 * AS_STRIDE + ac0) * 2, Ahi_g + (size_t)(bm0 + ar0) * K + k0 + ac0);
        cp_async16(sAh + (ar1 * AS_STRIDE + ac1) * 2, Ahi_g + (size_t)(bm0 + ar1) * K + k0 + ac1);
        cp_async16(sAl + (ar0 * AS_STRIDE + ac0) * 2, Alo_g + (size_t)(bm0 + ar0) * K + k0 + ac0);
        cp_async16(sAl + (ar1 * AS_STRIDE + ac1) * 2, Alo_g + (size_t)(bm0 + ar1) * K + k0 + ac1);
        cp_async16(sBh + (br0 * BS_STRIDE + bc0) * 2, Bhi_g + (size_t)(k0 + br0) * N + bn0 + bc0);
        cp_async16(sBh + (br1 * BS_STRIDE + bc1) * 2, Bhi_g + (size_t)(k0 + br1) * N + bn0 + bc1);
        cp_async16(sBl + (br0 * BS_STRIDE + bc0) * 2, Blo_g + (size_t)(k0 + br0) * N + bn0 + bc0);
        cp_async16(sBl + (br1 * BS_STRIDE + bc1) * 2, Blo_g + (size_t)(k0 + br1) * N + bn0 + bc1);
        cp_commit();
    };

    float c[4][4][4] = {};

    // prologue
    issue_stage(0, 0);

    for (int it = 0; it < NIT; it++) {
        const int s = it & 1;
        if (it + 1 < NIT) issue_stage(s ^ 1, (it + 1) * 32);

        if (it + 1 < NIT) cp_wait<1>(); else cp_wait<0>();
        __syncthreads();

        const __nv_bfloat16* S = gs + s * G_STAGE;
        const __nv_bfloat16* Ah = S + G_AH;
        const __nv_bfloat16* Al = S + G_AL;
        const __nv_bfloat16* Bh = S + G_BH;
        const __nv_bfloat16* Bl = S + G_BL;

#pragma unroll
        for (int ks = 0; ks < 32; ks += 16) {
            uint32_t ah[4][4], al[4][4], bh[4][2], bl[4][2];
            const int arow = wm * 64 + (lane & 15);
            const int acol = ks + (lane >> 4) * 8;
#pragma unroll
            for (int mi = 0; mi < 4; mi++) {
                ldsm_x4(ah[mi], smem_u32(Ah + (arow + mi * 16) * AS_STRIDE + acol));
                ldsm_x4(al[mi], smem_u32(Al + (arow + mi * 16) * AS_STRIDE + acol));
            }
            const int brow = ks + (lane & 15);
#pragma unroll
            for (int nj = 0; nj < 2; nj++) {
                const int bcol = wn * 32 + nj * 16 + (lane >> 4) * 8;
                uint32_t r[4];
                ldsm_x4_t(r, smem_u32(Bh + brow * BS_STRIDE + bcol));
                bh[nj * 2][0] = r[0]; bh[nj * 2][1] = r[1];
                bh[nj * 2 + 1][0] = r[2]; bh[nj * 2 + 1][1] = r[3];
                ldsm_x4_t(r, smem_u32(Bl + brow * BS_STRIDE + bcol));
                bl[nj * 2][0] = r[0]; bl[nj * 2][1] = r[1];
                bl[nj * 2 + 1][0] = r[2]; bl[nj * 2 + 1][1] = r[3];
            }
#pragma unroll
            for (int mi = 0; mi < 4; mi++)
#pragma unroll
                for (int ni = 0; ni < 4; ni++) {
                    mma_bf16(c[mi][ni], ah[mi], bh[ni]);
                    mma_bf16(c[mi][ni], ah[mi], bl[ni]);
                    mma_bf16(c[mi][ni], al[mi], bh[ni]);
                }
        }
        __syncthreads();
    }

    const int gid = lane >> 2, tig = lane & 3;
#pragma unroll
    for (int mi = 0; mi < 4; mi++) {
        const int r0 = bm0 + wm * 64 + mi * 16 + gid;
#pragma unroll
        for (int ni = 0; ni < 4; ni++) {
            const int cc = bn0 + wn * 32 + ni * 8 + tig * 2;
            *(float2*)&C[(size_t)r0 * N + cc] = make_float2(c[mi][ni][0], c[mi][ni][1]);
            *(float2*)&C[(size_t)(r0 + 8) * N + cc] = make_float2(c[mi][ni][2], c[mi][ni][3]);
        }
    }
}

// ---------------------------------------------------------------------------
// RoPE + split: read fp32 qkv, apply neox RoPE to q/k (v passthrough),
// write bf16 hi/lo head-major arrays [head][t][d].
// ---------------------------------------------------------------------------
__global__ void rope_split_kernel(const int* __restrict__ positions)
{
    const int t = blockIdx.x;
    const int hh = blockIdx.y;
    const int i = threadIdx.x;

    float y1, y2;
    __nv_bfloat16 *dst_hi, *dst_lo;

    if (hh < NH + NKV) {
        const int head_off = (hh < NH) ? hh : (NH + (hh - NH));
        const float* src = g_qkv + (size_t)t * QKV_N + head_off * HD;
        const float pos = (float)positions[t];
        const float inv_freq = powf(10000.0f, -(float)i * (1.0f / 128.0f));
        float s, c;
        sincosf(pos * inv_freq, &s, &c);
        const float x1 = src[i];
        const float x2 = src[i + 128];
        y1 = x1 * c - x2 * s;
        y2 = x2 * c + x1 * s;
        if (hh < NH) {
            dst_hi = g_q_hi + ((size_t)hh * T_SEQ + t) * HD;
            dst_lo = g_q_lo + ((size_t)hh * T_SEQ + t) * HD;
        } else {
            const int kvh = hh - NH;
            dst_hi = g_k_hi + ((size_t)kvh * T_SEQ + t) * HD;
            dst_lo = g_k_lo + ((size_t)kvh * T_SEQ + t) * HD;
        }
    } else {
        const int vh = hh - (NH + NKV);
        const float* src = g_qkv + (size_t)t * QKV_N + (NH + NKV + vh) * HD;
        y1 = src[i];
        y2 = src[i + 128];
        dst_hi = g_v_hi + ((size_t)vh * T_SEQ + t) * HD;
        dst_lo = g_v_lo + ((size_t)vh * T_SEQ + t) * HD;
    }

    __nv_bfloat16 h1, l1, h2, l2;
    split2(y1, h1, l1);
    split2(y2, h2, l2);
    dst_hi[i] = h1;        dst_lo[i] = l1;
    dst_hi[i + 128] = h2;  dst_lo[i + 128] = l2;
}

// ---------------------------------------------------------------------------
// Tensor-core flash attention (split-bf16), unchanged from R6.
// ---------------------------------------------------------------------------
#define ATS 264
#define ATILE (64 * ATS)
#define ATT2_SMEM_BYTES (6 * ATILE * 2)

__global__ __launch_bounds__(128, 1) void attn_mma_kernel()
{
    extern __shared__ __nv_bfloat16 sb[];
    __nv_bfloat16* SQh = sb;
    __nv_bfloat16* SQl = sb + ATILE;
    __nv_bfloat16* SKh = sb + 2 * ATILE;
    __nv_bfloat16* SKl = sb + 3 * ATILE;
    __nv_bfloat16* SVh = sb + 4 * ATILE;
    __nv_bfloat16* SVl = sb + 5 * ATILE;

    const int tid = threadIdx.x;
    const int lane = tid & 31;
    const int warp = tid >> 5;
    const int qt = (int)gridDim.x - 1 - (int)blockIdx.x;
    const int h = blockIdx.y;
    const int kvh = h >> 1;
    const int q0 = qt * 64;

    {
        const __nv_bfloat16* gqh = g_q_hi + ((size_t)h * T_SEQ + q0) * HD;
        const __nv_bfloat16* gql = g_q_lo + ((size_t)h * T_SEQ + q0) * HD;
        for (int it = tid; it < 64 * 32; it += 128) {
            int r = it >> 5, c = (it & 31) * 8;
            *(float4*)&SQh[r * ATS + c] = *(const float4*)(gqh + (size_t)r * HD + c);
            *(float4*)&SQl[r * ATS + c] = *(const float4*)(gql + (size_t)r * HD + c);
        }
    }

    float acc[32][4];
#pragma unroll
    for (int n = 0; n < 32; n++)
#pragma unroll
        for (int e = 0; e < 4; e++) acc[n][e] = 0.0f;
    float m0 = -INFINITY, m1 = -INFINITY, l0 = 0.0f, l1 = 0.0f;

    const float cap_mul = 0.0625f / 50.0f;

    const int qrow = warp * 16 + (lane & 15);
    const int qc8 = (lane >> 4) << 3;
    const int krow_b = ((lane >> 4) << 3) + (lane & 7);
    const int kc8 = ((lane >> 3) & 1) << 3;
    const int vrow_b = lane & 15;
    const int vc8 = (lane >> 4) << 3;

    const __nv_bfloat16* gkh = g_k_hi + (size_t)kvh * T_SEQ * HD;
    const __nv_bfloat16* gkl = g_k_lo + (size_t)kvh * T_SEQ * HD;
    const __nv_bfloat16* gvh = g_v_hi + (size_t)kvh * T_SEQ * HD;
    const __nv_bfloat16* gvl = g_v_lo + (size_t)kvh * T_SEQ * HD;

    for (int kt = 0; kt <= qt; kt++) {
        const int k0 = kt * 64;
        __syncthreads();
        for (int it = tid; it < 64 * 32; it += 128) {
            int r = it >> 5, c = (it & 31) * 8;
            size_t g = (size_t)(k0 + r) * HD + c;
            *(float4*)&SKh[r * ATS + c] = *(const float4*)(gkh + g);
            *(float4*)&SKl[r * ATS + c] = *(const float4*)(gkl + g);
            *(float4*)&SVh[r * ATS + c] = *(const float4*)(gvh + g);
            *(float4*)&SVl[r * ATS + c] = *(const float4*)(gvl + g);
        }
        __syncthreads();

        float sc[8][4];
#pragma unroll
        for (int n = 0; n < 8; n++)
#pragma unroll
            for (int e = 0; e < 4; e++) sc[n][e] = 0.0f;

#pragma unroll 2
        for (int ks = 0; ks < HD; ks += 16) {
            uint32_t aqh[4], aql[4];
            ldsm_x4(aqh, smem_u32(&SQh[qrow * ATS + ks + qc8]));
            ldsm_x4(aql, smem_u32(&SQl[qrow * ATS + ks + qc8]));
#pragma unroll
            for (int p4 = 0; p4 < 4; p4++) {
                uint32_t bh[4], bl[4];
                const int kr = p4 * 16 + krow_b;
                ldsm_x4(bh, smem_u32(&SKh[kr * ATS + ks + kc8]));
                ldsm_x4(bl, smem_u32(&SKl[kr * ATS + ks + kc8]));
                mma_bf16(sc[2 * p4], aqh, bh);
                mma_bf16(sc[2 * p4], aqh, bl);
                mma_bf16(sc[2 * p4], aql, bh);
                mma_bf16(sc[2 * p4 + 1], aqh, bh + 2);
                mma_bf16(sc[2 * p4 + 1], aqh, bl + 2);
                mma_bf16(sc[2 * p4 + 1], aql, bh + 2);
            }
        }

        const bool diag = (kt == qt);
        const int colb = k0 + 2 * (lane & 3);
        const int rowg = q0 + warp * 16 + (lane >> 2);
#pragma unroll
        for (int nt = 0; nt < 8; nt++) {
#pragma unroll
            for (int e = 0; e < 4; e++) {
                float z = 50.0f * tanhf(sc[nt][e] * cap_mul);
                if (diag) {
                    int col = colb + nt * 8 + (e & 1);
                    int row = rowg + ((e >> 1) << 3);
                    if (col > row) z = -INFINITY;
                }
                sc[nt][e] = z;
            }
        }

        float rm0 = -INFINITY, rm1 = -INFINITY;
#pragma unroll
        for (int nt = 0; nt < 8; nt++) {
            rm0 = fmaxf(rm0, fmaxf(sc[nt][0], sc[nt][1]));
            rm1 = fmaxf(rm1, fmaxf(sc[nt][2], sc[nt][3]));
        }
        rm0 = fmaxf(rm0, __shfl_xor_sync(0xffffffffu, rm0, 1));
        rm0 = fmaxf(rm0, __shfl_xor_sync(0xffffffffu, rm0, 2));
        rm1 = fmaxf(rm1, __shfl_xor_sync(0xffffffffu, rm1, 1));
        rm1 = fmaxf(rm1, __shfl_xor_sync(0xffffffffu, rm1, 2));

        const float nm0 = fmaxf(m0, rm0);
        const float nm1 = fmaxf(m1, rm1);
        const float cr0 = __expf(m0 - nm0);
        const float cr1 = __expf(m1 - nm1);

        float ps0 = 0.0f, ps1 = 0.0f;
#pragma unroll
        for (int nt = 0; nt < 8; nt++) {
            float p0 = __expf(sc[nt][0] - nm0);
            float p1 = __expf(sc[nt][1] - nm0);
            float p2 = __expf(sc[nt][2] - nm1);
            float p3 = __expf(sc[nt][3] - nm1);
            sc[nt][0] = p0; sc[nt][1] = p1; sc[nt][2] = p2; sc[nt][3] = p3;
            ps0 += p0 + p1;
            ps1 += p2 + p3;
        }
        ps0 += __shfl_xor_sync(0xffffffffu, ps0, 1);
        ps0 += __shfl_xor_sync(0xffffffffu, ps0, 2);
        ps1 += __shfl_xor_sync(0xffffffffu, ps1, 1);
        ps1 += __shfl_xor_sync(0xffffffffu, ps1, 2);

        l0 = l0 * cr0 + ps0;
        l1 = l1 * cr1 + ps1;
        m0 = nm0; m1 = nm1;

#pragma unroll
        for (int n = 0; n < 32; n++) {
            acc[n][0] *= cr0; acc[n][1] *= cr0;
            acc[n][2] *= cr1; acc[n][3] *= cr1;
        }

        uint32_t ph[4][4], pl[4][4];
#pragma unroll
        for (int j = 0; j < 4; j++) {
            __nv_bfloat16 h0, lo0, h1, lo1;
#pragma unroll
            for (int half = 0; half < 2; half++) {
                const int nt = 2 * j + half;
                split2(sc[nt][0], h0, lo0);
                split2(sc[nt][1], h1, lo1);
                ph[j][2 * half] = pack_bf2(h0, h1);
                pl[j][2 * half] = pack_bf2(lo0, lo1);
                split2(sc[nt][2], h0, lo0);
                split2(sc[nt][3], h1, lo1);
                ph[j][2 * half + 1] = pack_bf2(h0, h1);
                pl[j][2 * half + 1] = pack_bf2(lo0, lo1);
            }
        }

#pragma unroll
        for (int kk = 0; kk < 4; kk++) {
            const int vr = kk * 16 + vrow_b;
#pragma unroll
            for (int np = 0; np < 16; np++) {
                uint32_t bvh[4], bvl[4];
                const int vc = np * 16 + vc8;
                ldsm_x4_t(bvh, smem_u32(&SVh[vr * ATS + vc]));
                ldsm_x4_t(bvl, smem_u32(&SVl[vr * ATS + vc]));
                mma_bf16(acc[2 * np], ph[kk], bvh);
                mma_bf16(acc[2 * np], ph[kk], bvl);
                mma_bf16(acc[2 * np], pl[kk], bvh);
                mma_bf16(acc[2 * np + 1], ph[kk], bvh + 2);
                mma_bf16(acc[2 * np + 1], ph[kk], bvl + 2);
                mma_bf16(acc[2 * np + 1], pl[kk], bvh + 2);
            }
        }
    }

    const float il0 = 1.0f / l0;
    const float il1 = 1.0f / l1;
    const size_t rowA = (size_t)(q0 + warp * 16 + (lane >> 2));
    const size_t rowB = rowA + 8;
    const int cb = h * HD + 2 * (lane & 3);
#pragma unroll
    for (int nt = 0; nt < 32; nt++) {
        const int c = cb + nt * 8;
        float o0 = acc[nt][0] * il0, o1 = acc[nt][1] * il0;
        float o2 = acc[nt][2] * il1, o3 = acc[nt][3] * il1;
        __nv_bfloat16 h0, lo0, h1, lo1;
        split2(o0, h0, lo0); split2(o1, h1, lo1);
        *(uint32_t*)&g_att_hi[rowA * ATT_N + c] = pack_bf2(h0, h1);
        *(uint32_t*)&g_att_lo[rowA * ATT_N + c] = pack_bf2(lo0, lo1);
        split2(o2, h0, lo0); split2(o3, h1, lo1);
        *(uint32_t*)&g_att_hi[rowB * ATT_N + c] = pack_bf2(h0, h1);
        *(uint32_t*)&g_att_lo[rowB * ATT_N + c] = pack_bf2(lo0, lo1);
    }
}

// ---------------------------------------------------------------------------
// kernel_launch
// ---------------------------------------------------------------------------
extern "C" void kernel_launch(void* const* d_in, const int* in_sizes, int n_in,
                              void* d_out, int out_size)
{
    const int*   positions = (const int*)d_in[0];
    const float* hidden    = (const float*)d_in[1];
    const float* w_qkv     = (const float*)d_in[2];
    const float* w_o       = (const float*)d_in[3];
    float* out = (float*)d_out;

    float* qkv_ptr = nullptr;
    __nv_bfloat16 *hid_hi, *hid_lo, *wqkv_hi, *wqkv_lo, *wo_hi, *wo_lo, *att_hi, *att_lo;
    cudaGetSymbolAddress((void**)&qkv_ptr, g_qkv);
    cudaGetSymbolAddress((void**)&hid_hi, g_hid_hi);
    cudaGetSymbolAddress((void**)&hid_lo, g_hid_lo);
    cudaGetSymbolAddress((void**)&wqkv_hi, g_wqkv_hi);
    cudaGetSymbolAddress((void**)&wqkv_lo, g_wqkv_lo);
    cudaGetSymbolAddress((void**)&wo_hi, g_wo_hi);
    cudaGetSymbolAddress((void**)&wo_lo, g_wo_lo);
    cudaGetSymbolAddress((void**)&att_hi, g_att_hi);
    cudaGetSymbolAddress((void**)&att_lo, g_att_lo);

    // 0) Split inputs into bf16 hi/lo
    {
        size_t n1 = (size_t)T_SEQ * HID;
        split_kernel<<<(unsigned)((n1 / 4 + 255) / 256), 256>>>(hidden, hid_hi, hid_lo, n1);
        size_t n2 = (size_t)HID * QKV_N;
        split_kernel<<<(unsigned)((n2 / 4 + 255) / 256), 256>>>(w_qkv, wqkv_hi, wqkv_lo, n2);
        size_t n3 = (size_t)ATT_N * HID;
        split_kernel<<<(unsigned)((n3 / 4 + 255) / 256), 256>>>(w_o, wo_hi, wo_lo, n3);
    }

    // 1) QKV projection (pipelined split-bf16 tensor GEMM)
    {
        cudaFuncSetAttribute(bgemm3_kernel,
                             cudaFuncAttributeMaxDynamicSharedMemorySize,
                             GEMM_SMEM_BYTES);
        dim3 grid(QKV_N / 128, T_SEQ / 128);
        bgemm3_kernel<<<grid, 256, GEMM_SMEM_BYTES>>>(
            hid_hi, hid_lo, wqkv_hi, wqkv_lo, qkv_ptr, T_SEQ, QKV_N, HID);
    }

    // 2) RoPE + split to head-major bf16 hi/lo Q/K/V
    rope_split_kernel<<<dim3(T_SEQ, NH + 2 * NKV), 128>>>(positions);

    // 3) Tensor-core flash attention -> att_hi/att_lo
    {
        cudaFuncSetAttribute(attn_mma_kernel,
                             cudaFuncAttributeMaxDynamicSharedMemorySize,
                             ATT2_SMEM_BYTES);
        attn_mma_kernel<<<dim3(T_SEQ / 64, NH), 128, ATT2_SMEM_BYTES>>>();
    }

    // 4) O projection (pipelined split-bf16 tensor GEMM)
    {
        dim3 grid(HID / 128, T_SEQ / 128);
        bgemm3_kernel<<<grid, 256, GEMM_SMEM_BYTES>>>(
            att_hi, att_lo, wo_hi, wo_lo, out, T_SEQ, HID, ATT_N);
    }
}

// round 12
// speedup vs baseline: 3.5923x; 1.0286x over previous
#include <cuda_runtime.h>
#include <cuda_bf16.h>
#include <math.h>
#include <stdint.h>

// Problem constants
#define T_SEQ 2048
#define HID 3584
#define NH 16
#define NKV 8
#define HD 256
#define QKV_N ((NH + 2 * NKV) * HD)   // 8192
#define ATT_N (NH * HD)               // 4096

// Scratch (static device globals — no runtime allocation)
__device__ float g_qkv[(size_t)T_SEQ * QKV_N];    // 64 MB

// bf16 hi/lo splits for tensor-core GEMMs (R8 layout: weights row-major [K][N])
__device__ __nv_bfloat16 g_hid_hi[(size_t)T_SEQ * HID];
__device__ __nv_bfloat16 g_hid_lo[(size_t)T_SEQ * HID];
__device__ __nv_bfloat16 g_wqkv_hi[(size_t)HID * QKV_N];
__device__ __nv_bfloat16 g_wqkv_lo[(size_t)HID * QKV_N];
__device__ __nv_bfloat16 g_wo_hi[(size_t)ATT_N * HID];
__device__ __nv_bfloat16 g_wo_lo[(size_t)ATT_N * HID];
__device__ __nv_bfloat16 g_att_hi[(size_t)T_SEQ * ATT_N];
__device__ __nv_bfloat16 g_att_lo[(size_t)T_SEQ * ATT_N];

// head-major post-RoPE Q/K/V splits for attention: [head][t][d]
__device__ __nv_bfloat16 g_q_hi[(size_t)NH * T_SEQ * HD];
__device__ __nv_bfloat16 g_q_lo[(size_t)NH * T_SEQ * HD];
__device__ __nv_bfloat16 g_k_hi[(size_t)NKV * T_SEQ * HD];
__device__ __nv_bfloat16 g_k_lo[(size_t)NKV * T_SEQ * HD];
__device__ __nv_bfloat16 g_v_hi[(size_t)NKV * T_SEQ * HD];
__device__ __nv_bfloat16 g_v_lo[(size_t)NKV * T_SEQ * HD];

// ---------------------------------------------------------------------------
// helpers
// ---------------------------------------------------------------------------
__device__ __forceinline__ uint32_t smem_u32(const void* p) {
    return (uint32_t)__cvta_generic_to_shared(p);
}
__device__ __forceinline__ void ldsm_x4(uint32_t* r, uint32_t addr) {
    asm volatile("ldmatrix.sync.aligned.m8n8.x4.shared.b16 {%0,%1,%2,%3}, [%4];\n"
                 : "=r"(r[0]), "=r"(r[1]), "=r"(r[2]), "=r"(r[3]) : "r"(addr));
}
__device__ __forceinline__ void ldsm_x4_t(uint32_t* r, uint32_t addr) {
    asm volatile("ldmatrix.sync.aligned.m8n8.x4.trans.shared.b16 {%0,%1,%2,%3}, [%4];\n"
                 : "=r"(r[0]), "=r"(r[1]), "=r"(r[2]), "=r"(r[3]) : "r"(addr));
}
__device__ __forceinline__ void mma_bf16(float* c, const uint32_t* a, const uint32_t* b) {
    asm volatile(
        "mma.sync.aligned.m16n8k16.row.col.f32.bf16.bf16.f32 "
        "{%0,%1,%2,%3}, {%4,%5,%6,%7}, {%8,%9}, {%0,%1,%2,%3};\n"
        : "+f"(c[0]), "+f"(c[1]), "+f"(c[2]), "+f"(c[3])
        : "r"(a[0]), "r"(a[1]), "r"(a[2]), "r"(a[3]), "r"(b[0]), "r"(b[1]));
}
__device__ __forceinline__ void cp_async16(uint32_t smem_addr, const void* gptr) {
    asm volatile("cp.async.cg.shared.global [%0], [%1], 16;\n"
                 :: "r"(smem_addr), "l"(gptr));
}
__device__ __forceinline__ void cp_commit() {
    asm volatile("cp.async.commit_group;\n");
}
template <int N>
__device__ __forceinline__ void cp_wait() {
    asm volatile("cp.async.wait_group %0;\n" :: "n"(N));
}
__device__ __forceinline__ void split2(float x, __nv_bfloat16& h, __nv_bfloat16& l) {
    h = __float2bfloat16_rn(x);
    l = __float2bfloat16_rn(x - __bfloat162float(h));
}
__device__ __forceinline__ uint32_t pack_bf2(__nv_bfloat16 a, __nv_bfloat16 b) {
    __nv_bfloat162 t;
    t.x = a; t.y = b;
    uint32_t r;
    memcpy(&r, &t, 4);
    return r;
}

// ---------------------------------------------------------------------------
// Split fp32 -> bf16 hi + bf16 lo (residual). n must be multiple of 4.
// ---------------------------------------------------------------------------
__global__ void split_kernel(const float* __restrict__ x,
                             __nv_bfloat16* __restrict__ hi,
                             __nv_bfloat16* __restrict__ lo, size_t n)
{
    size_t i = ((size_t)blockIdx.x * blockDim.x + threadIdx.x) * 4;
    if (i >= n) return;
    float4 v = *(const float4*)(x + i);
    __nv_bfloat16 h[4], l[4];
    float vv[4] = {v.x, v.y, v.z, v.w};
#pragma unroll
    for (int j = 0; j < 4; j++) split2(vv[j], h[j], l[j]);
    *(uint2*)(hi + i) = *(uint2*)h;
    *(uint2*)(lo + i) = *(uint2*)l;
}

// ---------------------------------------------------------------------------
// Split-bf16 tensor-core GEMM with 2-stage cp.async pipeline (R8, proven).
// ---------------------------------------------------------------------------
#define AS_STRIDE 40
#define BS_STRIDE 136
#define G_AH 0
#define G_AL (128 * AS_STRIDE)
#define G_BH (2 * 128 * AS_STRIDE)
#define G_BL (2 * 128 * AS_STRIDE + 32 * BS_STRIDE)
#define G_STAGE (2 * 128 * AS_STRIDE + 2 * 32 * BS_STRIDE)
#define GEMM_SMEM_BYTES (2 * G_STAGE * 2)

__global__ __launch_bounds__(256) void bgemm3_kernel(
    const __nv_bfloat16* __restrict__ Ahi_g, const __nv_bfloat16* __restrict__ Alo_g,
    const __nv_bfloat16* __restrict__ Bhi_g, const __nv_bfloat16* __restrict__ Blo_g,
    float* __restrict__ C, int M, int N, int K)
{
    extern __shared__ __nv_bfloat16 gs[];

    const int tid = threadIdx.x;
    const int wid = tid >> 5;
    const int lane = tid & 31;
    const int wm = wid & 1;
    const int wn = wid >> 1;

    const int bm0 = blockIdx.y * 128;
    const int bn0 = blockIdx.x * 128;

    const int ch0 = tid, ch1 = tid + 256;
    const int ar0 = ch0 >> 2, ac0 = (ch0 & 3) * 8;
    const int ar1 = ch1 >> 2, ac1 = (ch1 & 3) * 8;
    const int br0 = ch0 >> 4, bc0 = (ch0 & 15) * 8;
    const int br1 = ch1 >> 4, bc1 = (ch1 & 15) * 8;

    const int NIT = K / 32;

    auto issue_stage = [&](int stage, int k0) {
        __nv_bfloat16* S = gs + stage * G_STAGE;
        uint32_t sAh = smem_u32(S + G_AH);
        uint32_t sAl = smem_u32(S + G_AL);
        uint32_t sBh = smem_u32(S + G_BH);
        uint32_t sBl = smem_u32(S + G_BL);
        cp_async16(sAh + (ar0 * AS_STRIDE + ac0) * 2, Ahi_g + (size_t)(bm0 + ar0) * K + k0 + ac0);
        cp_async16(sAh + (ar1 * AS_STRIDE + ac1) * 2, Ahi_g + (size_t)(bm0 + ar1) * K + k0 + ac1);
        cp_async16(sAl + (ar0 * AS_STRIDE + ac0) * 2, Alo_g + (size_t)(bm0 + ar0) * K + k0 + ac0);
        cp_async16(sAl + (ar1 * AS_STRIDE + ac1) * 2, Alo_g + (size_t)(bm0 + ar1) * K + k0 + ac1);
        cp_async16(sBh + (br0 * BS_STRIDE + bc0) * 2, Bhi_g + (size_t)(k0 + br0) * N + bn0 + bc0);
        cp_async16(sBh + (br1 * BS_STRIDE + bc1) * 2, Bhi_g + (size_t)(k0 + br1) * N + bn0 + bc1);
        cp_async16(sBl + (br0 * BS_STRIDE + bc0) * 2, Blo_g + (size_t)(k0 + br0) * N + bn0 + bc0);
        cp_async16(sBl + (br1 * BS_STRIDE + bc1) * 2, Blo_g + (size_t)(k0 + br1) * N + bn0 + bc1);
        cp_commit();
    };

    float c[4][4][4] = {};

    issue_stage(0, 0);

    for (int it = 0; it < NIT; it++) {
        const int s = it & 1;
        if (it + 1 < NIT) issue_stage(s ^ 1, (it + 1) * 32);

        if (it + 1 < NIT) cp_wait<1>(); else cp_wait<0>();
        __syncthreads();

        const __nv_bfloat16* S = gs + s * G_STAGE;
        const __nv_bfloat16* Ah = S + G_AH;
        const __nv_bfloat16* Al = S + G_AL;
        const __nv_bfloat16* Bh = S + G_BH;
        const __nv_bfloat16* Bl = S + G_BL;

#pragma unroll
        for (int ks = 0; ks < 32; ks += 16) {
            uint32_t ah[4][4], al[4][4], bh[4][2], bl[4][2];
            const int arow = wm * 64 + (lane & 15);
            const int acol = ks + (lane >> 4) * 8;
#pragma unroll
            for (int mi = 0; mi < 4; mi++) {
                ldsm_x4(ah[mi], smem_u32(Ah + (arow + mi * 16) * AS_STRIDE + acol));
                ldsm_x4(al[mi], smem_u32(Al + (arow + mi * 16) * AS_STRIDE + acol));
            }
            const int brow = ks + (lane & 15);
#pragma unroll
            for (int nj = 0; nj < 2; nj++) {
                const int bcol = wn * 32 + nj * 16 + (lane >> 4) * 8;
                uint32_t r[4];
                ldsm_x4_t(r, smem_u32(Bh + brow * BS_STRIDE + bcol));
                bh[nj * 2][0] = r[0]; bh[nj * 2][1] = r[1];
                bh[nj * 2 + 1][0] = r[2]; bh[nj * 2 + 1][1] = r[3];
                ldsm_x4_t(r, smem_u32(Bl + brow * BS_STRIDE + bcol));
                bl[nj * 2][0] = r[0]; bl[nj * 2][1] = r[1];
                bl[nj * 2 + 1][0] = r[2]; bl[nj * 2 + 1][1] = r[3];
            }
#pragma unroll
            for (int mi = 0; mi < 4; mi++)
#pragma unroll
                for (int ni = 0; ni < 4; ni++) {
                    mma_bf16(c[mi][ni], ah[mi], bh[ni]);
                    mma_bf16(c[mi][ni], ah[mi], bl[ni]);
                    mma_bf16(c[mi][ni], al[mi], bh[ni]);
                }
        }
        __syncthreads();
    }

    const int gid = lane >> 2, tig = lane & 3;
#pragma unroll
    for (int mi = 0; mi < 4; mi++) {
        const int r0 = bm0 + wm * 64 + mi * 16 + gid;
#pragma unroll
        for (int ni = 0; ni < 4; ni++) {
            const int cc = bn0 + wn * 32 + ni * 8 + tig * 2;
            *(float2*)&C[(size_t)r0 * N + cc] = make_float2(c[mi][ni][0], c[mi][ni][1]);
            *(float2*)&C[(size_t)(r0 + 8) * N + cc] = make_float2(c[mi][ni][2], c[mi][ni][3]);
        }
    }
}

// ---------------------------------------------------------------------------
// RoPE + split: read fp32 qkv, apply neox RoPE to q/k (v passthrough),
// write bf16 hi/lo head-major arrays [head][t][d].
// ---------------------------------------------------------------------------
__global__ void rope_split_kernel(const int* __restrict__ positions)
{
    const int t = blockIdx.x;
    const int hh = blockIdx.y;
    const int i = threadIdx.x;

    float y1, y2;
    __nv_bfloat16 *dst_hi, *dst_lo;

    if (hh < NH + NKV) {
        const int head_off = (hh < NH) ? hh : (NH + (hh - NH));
        const float* src = g_qkv + (size_t)t * QKV_N + head_off * HD;
        const float pos = (float)positions[t];
        const float inv_freq = powf(10000.0f, -(float)i * (1.0f / 128.0f));
        float s, c;
        sincosf(pos * inv_freq, &s, &c);
        const float x1 = src[i];
        const float x2 = src[i + 128];
        y1 = x1 * c - x2 * s;
        y2 = x2 * c + x1 * s;
        if (hh < NH) {
            dst_hi = g_q_hi + ((size_t)hh * T_SEQ + t) * HD;
            dst_lo = g_q_lo + ((size_t)hh * T_SEQ + t) * HD;
        } else {
            const int kvh = hh - NH;
            dst_hi = g_k_hi + ((size_t)kvh * T_SEQ + t) * HD;
            dst_lo = g_k_lo + ((size_t)kvh * T_SEQ + t) * HD;
        }
    } else {
        const int vh = hh - (NH + NKV);
        const float* src = g_qkv + (size_t)t * QKV_N + (NH + NKV + vh) * HD;
        y1 = src[i];
        y2 = src[i + 128];
        dst_hi = g_v_hi + ((size_t)vh * T_SEQ + t) * HD;
        dst_lo = g_v_lo + ((size_t)vh * T_SEQ + t) * HD;
    }

    __nv_bfloat16 h1, l1, h2, l2;
    split2(y1, h1, l1);
    split2(y2, h2, l2);
    dst_hi[i] = h1;        dst_lo[i] = l1;
    dst_hi[i + 128] = h2;  dst_lo[i + 128] = l2;
}

// ---------------------------------------------------------------------------
// Tensor-core flash attention (split-bf16) with 2-stage cp.async K/V pipeline.
// Block = (q-tile 64, head), 128 threads = 4 warps (16 q-rows per warp).
// K/V tiles are 32 keys, double-buffered. smem = 202752 B (as R8).
// ---------------------------------------------------------------------------
#define ATS 264
#define AQ_TILE (64 * ATS)
#define AKV_TILE (32 * ATS)
#define ATT2_SMEM_BYTES ((2 * AQ_TILE + 8 * AKV_TILE) * 2)   // 202752

__global__ __launch_bounds__(128, 1) void attn_mma_kernel()
{
    extern __shared__ __nv_bfloat16 sb[];
    __nv_bfloat16* SQh = sb;
    __nv_bfloat16* SQl = sb + AQ_TILE;

    const int tid = threadIdx.x;
    const int lane = tid & 31;
    const int warp = tid >> 5;
    const int qt = (int)gridDim.x - 1 - (int)blockIdx.x;
    const int h = blockIdx.y;
    const int kvh = h >> 1;
    const int q0 = qt * 64;

    // ---- load Q tile (once) ----
    {
        const __nv_bfloat16* gqh = g_q_hi + ((size_t)h * T_SEQ + q0) * HD;
        const __nv_bfloat16* gql = g_q_lo + ((size_t)h * T_SEQ + q0) * HD;
        for (int it = tid; it < 64 * 32; it += 128) {
            int r = it >> 5, c = (it & 31) * 8;
            *(float4*)&SQh[r * ATS + c] = *(const float4*)(gqh + (size_t)r * HD + c);
            *(float4*)&SQl[r * ATS + c] = *(const float4*)(gql + (size_t)r * HD + c);
        }
    }

    float acc[32][4];
#pragma unroll
    for (int n = 0; n < 32; n++)
#pragma unroll
        for (int e = 0; e < 4; e++) acc[n][e] = 0.0f;
    float m0 = -INFINITY, m1 = -INFINITY, l0 = 0.0f, l1 = 0.0f;

    const float cap_mul = 0.0625f / 50.0f;   // SCALE / SOFT_CAP

    const int qrow = warp * 16 + (lane & 15);
    const int qc8 = (lane >> 4) << 3;
    const int krow_b = ((lane >> 4) << 3) + (lane & 7);
    const int kc8 = ((lane >> 3) & 1) << 3;
    const int vrow_b = lane & 15;
    const int vc8 = (lane >> 4) << 3;

    const __nv_bfloat16* gkh = g_k_hi + (size_t)kvh * T_SEQ * HD;
    const __nv_bfloat16* gkl = g_k_lo + (size_t)kvh * T_SEQ * HD;
    const __nv_bfloat16* gvh = g_v_hi + (size_t)kvh * T_SEQ * HD;
    const __nv_bfloat16* gvl = g_v_lo + (size_t)kvh * T_SEQ * HD;

    const int NKT = 2 * (qt + 1);   // 32-key tiles

    auto issue_kv = [&](int t) {
        __nv_bfloat16* S = sb + 2 * AQ_TILE + (size_t)(t & 1) * 4 * AKV_TILE;
        const uint32_t skh = smem_u32(S);
        const uint32_t skl = smem_u32(S + AKV_TILE);
        const uint32_t svh = smem_u32(S + 2 * AKV_TILE);
        const uint32_t svl = smem_u32(S + 3 * AKV_TILE);
        const int k0 = t * 32;
#pragma unroll
        for (int i = 0; i < 8; i++) {
            int it = tid + i * 128;           // 0..1023
            int r = it >> 5, c = (it & 31) * 8;
            const size_t g = (size_t)(k0 + r) * HD + c;
            const uint32_t off = (uint32_t)(r * ATS + c) * 2;
            cp_async16(skh + off, gkh + g);
            cp_async16(skl + off, gkl + g);
            cp_async16(svh + off, gvh + g);
            cp_async16(svl + off, gvl + g);
        }
        cp_commit();
    };

    issue_kv(0);

    for (int t = 0; t < NKT; t++) {
        if (t + 1 < NKT) { issue_kv(t + 1); cp_wait<1>(); }
        else             { cp_wait<0>(); }
        __syncthreads();

        __nv_bfloat16* S = sb + 2 * AQ_TILE + (size_t)(t & 1) * 4 * AKV_TILE;
        __nv_bfloat16* SKh = S;
        __nv_bfloat16* SKl = S + AKV_TILE;
        __nv_bfloat16* SVh = S + 2 * AKV_TILE;
        __nv_bfloat16* SVl = S + 3 * AKV_TILE;
        const int k0 = t * 32;

        // ---- S = Q K^T (64x32), split 3-MMA ----
        float sc[4][4];
#pragma unroll
        for (int n = 0; n < 4; n++)
#pragma unroll
            for (int e = 0; e < 4; e++) sc[n][e] = 0.0f;

#pragma unroll 4
        for (int ks = 0; ks < HD; ks += 16) {
            uint32_t aqh[4], aql[4];
            ldsm_x4(aqh, smem_u32(&SQh[qrow * ATS + ks + qc8]));
            ldsm_x4(aql, smem_u32(&SQl[qrow * ATS + ks + qc8]));
#pragma unroll
            for (int p4 = 0; p4 < 2; p4++) {
                uint32_t bh[4], bl[4];
                const int kr = p4 * 16 + krow_b;
                ldsm_x4(bh, smem_u32(&SKh[kr * ATS + ks + kc8]));
                ldsm_x4(bl, smem_u32(&SKl[kr * ATS + ks + kc8]));
                mma_bf16(sc[2 * p4], aqh, bh);
                mma_bf16(sc[2 * p4], aqh, bl);
                mma_bf16(sc[2 * p4], aql, bh);
                mma_bf16(sc[2 * p4 + 1], aqh, bh + 2);
                mma_bf16(sc[2 * p4 + 1], aqh, bl + 2);
                mma_bf16(sc[2 * p4 + 1], aql, bh + 2);
            }
        }

        // ---- soft-cap + causal mask (last two tiles overlap diagonal) ----
        const bool diag = (t >= NKT - 2);
        const int colb = k0 + 2 * (lane & 3);
        const int rowg = q0 + warp * 16 + (lane >> 2);
#pragma unroll
        for (int nt = 0; nt < 4; nt++) {
#pragma unroll
            for (int e = 0; e < 4; e++) {
                float z = 50.0f * tanhf(sc[nt][e] * cap_mul);
                if (diag) {
                    int col = colb + nt * 8 + (e & 1);
                    int row = rowg + ((e >> 1) << 3);
                    if (col > row) z = -INFINITY;
                }
                sc[nt][e] = z;
            }
        }

        // ---- online softmax (rows g and g+8) ----
        float rm0 = -INFINITY, rm1 = -INFINITY;
#pragma unroll
        for (int nt = 0; nt < 4; nt++) {
            rm0 = fmaxf(rm0, fmaxf(sc[nt][0], sc[nt][1]));
            rm1 = fmaxf(rm1, fmaxf(sc[nt][2], sc[nt][3]));
        }
        rm0 = fmaxf(rm0, __shfl_xor_sync(0xffffffffu, rm0, 1));
        rm0 = fmaxf(rm0, __shfl_xor_sync(0xffffffffu, rm0, 2));
        rm1 = fmaxf(rm1, __shfl_xor_sync(0xffffffffu, rm1, 1));
        rm1 = fmaxf(rm1, __shfl_xor_sync(0xffffffffu, rm1, 2));

        const float nm0 = fmaxf(m0, rm0);
        const float nm1 = fmaxf(m1, rm1);
        const float cr0 = __expf(m0 - nm0);
        const float cr1 = __expf(m1 - nm1);

        float ps0 = 0.0f, ps1 = 0.0f;
#pragma unroll
        for (int nt = 0; nt < 4; nt++) {
            float p0 = __expf(sc[nt][0] - nm0);
            float p1 = __expf(sc[nt][1] - nm0);
            float p2 = __expf(sc[nt][2] - nm1);
            float p3 = __expf(sc[nt][3] - nm1);
            sc[nt][0] = p0; sc[nt][1] = p1; sc[nt][2] = p2; sc[nt][3] = p3;
            ps0 += p0 + p1;
            ps1 += p2 + p3;
        }
        ps0 += __shfl_xor_sync(0xffffffffu, ps0, 1);
        ps0 += __shfl_xor_sync(0xffffffffu, ps0, 2);
        ps1 += __shfl_xor_sync(0xffffffffu, ps1, 1);
        ps1 += __shfl_xor_sync(0xffffffffu, ps1, 2);

        l0 = l0 * cr0 + ps0;
        l1 = l1 * cr1 + ps1;
        m0 = nm0; m1 = nm1;

#pragma unroll
        for (int n = 0; n < 32; n++) {
            acc[n][0] *= cr0; acc[n][1] *= cr0;
            acc[n][2] *= cr1; acc[n][3] *= cr1;
        }

        // ---- convert P (16x32) to split-bf16 A-fragments ----
        uint32_t ph[2][4], pl[2][4];
#pragma unroll
        for (int j = 0; j < 2; j++) {
            __nv_bfloat16 h0, lo0, h1, lo1;
#pragma unroll
            for (int half = 0; half < 2; half++) {
                const int nt = 2 * j + half;
                split2(sc[nt][0], h0, lo0);
                split2(sc[nt][1], h1, lo1);
                ph[j][2 * half] = pack_bf2(h0, h1);
                pl[j][2 * half] = pack_bf2(lo0, lo1);
                split2(sc[nt][2], h0, lo0);
                split2(sc[nt][3], h1, lo1);
                ph[j][2 * half + 1] = pack_bf2(h0, h1);
                pl[j][2 * half + 1] = pack_bf2(lo0, lo1);
            }
        }

        // ---- acc += P V (16x32 @ 32x256), split 3-MMA ----
#pragma unroll
        for (int kk = 0; kk < 2; kk++) {
            const int vr = kk * 16 + vrow_b;
#pragma unroll
            for (int np = 0; np < 16; np++) {
                uint32_t bvh[4], bvl[4];
                const int vc = np * 16 + vc8;
                ldsm_x4_t(bvh, smem_u32(&SVh[vr * ATS + vc]));
                ldsm_x4_t(bvl, smem_u32(&SVl[vr * ATS + vc]));
                mma_bf16(acc[2 * np], ph[kk], bvh);
                mma_bf16(acc[2 * np], ph[kk], bvl);
                mma_bf16(acc[2 * np], pl[kk], bvh);
                mma_bf16(acc[2 * np + 1], ph[kk], bvh + 2);
                mma_bf16(acc[2 * np + 1], ph[kk], bvl + 2);
                mma_bf16(acc[2 * np + 1], pl[kk], bvh + 2);
            }
        }
        __syncthreads();   // all warps done reading this stage before reuse
    }

    // ---- epilogue: normalize, split to bf16 hi/lo, store ----
    const float il0 = 1.0f / l0;
    const float il1 = 1.0f / l1;
    const size_t rowA = (size_t)(q0 + warp * 16 + (lane >> 2));
    const size_t rowB = rowA + 8;
    const int cb = h * HD + 2 * (lane & 3);
#pragma unroll
    for (int nt = 0; nt < 32; nt++) {
        const int c = cb + nt * 8;
        float o0 = acc[nt][0] * il0, o1 = acc[nt][1] * il0;
        float o2 = acc[nt][2] * il1, o3 = acc[nt][3] * il1;
        __nv_bfloat16 h0, lo0, h1, lo1;
        split2(o0, h0, lo0); split2(o1, h1, lo1);
        *(uint32_t*)&g_att_hi[rowA * ATT_N + c] = pack_bf2(h0, h1);
        *(uint32_t*)&g_att_lo[rowA * ATT_N + c] = pack_bf2(lo0, lo1);
        split2(o2, h0, lo0); split2(o3, h1, lo1);
        *(uint32_t*)&g_att_hi[rowB * ATT_N + c] = pack_bf2(h0, h1);
        *(uint32_t*)&g_att_lo[rowB * ATT_N + c] = pack_bf2(lo0, lo1);
    }
}

// ---------------------------------------------------------------------------
// kernel_launch
// ---------------------------------------------------------------------------
extern "C" void kernel_launch(void* const* d_in, const int* in_sizes, int n_in,
                              void* d_out, int out_size)
{
    const int*   positions = (const int*)d_in[0];
    const float* hidden    = (const float*)d_in[1];
    const float* w_qkv     = (const float*)d_in[2];
    const float* w_o       = (const float*)d_in[3];
    float* out = (float*)d_out;

    float* qkv_ptr = nullptr;
    __nv_bfloat16 *hid_hi, *hid_lo, *wqkv_hi, *wqkv_lo, *wo_hi, *wo_lo, *att_hi, *att_lo;
    cudaGetSymbolAddress((void**)&qkv_ptr, g_qkv);
    cudaGetSymbolAddress((void**)&hid_hi, g_hid_hi);
    cudaGetSymbolAddress((void**)&hid_lo, g_hid_lo);
    cudaGetSymbolAddress((void**)&wqkv_hi, g_wqkv_hi);
    cudaGetSymbolAddress((void**)&wqkv_lo, g_wqkv_lo);
    cudaGetSymbolAddress((void**)&wo_hi, g_wo_hi);
    cudaGetSymbolAddress((void**)&wo_lo, g_wo_lo);
    cudaGetSymbolAddress((void**)&att_hi, g_att_hi);
    cudaGetSymbolAddress((void**)&att_lo, g_att_lo);

    // 0) Split inputs into bf16 hi/lo
    {
        size_t n1 = (size_t)T_SEQ * HID;
        split_kernel<<<(unsigned)((n1 / 4 + 255) / 256), 256>>>(hidden, hid_hi, hid_lo, n1);
        size_t n2 = (size_t)HID * QKV_N;
        split_kernel<<<(unsigned)((n2 / 4 + 255) / 256), 256>>>(w_qkv, wqkv_hi, wqkv_lo, n2);
        size_t n3 = (size_t)ATT_N * HID;
        split_kernel<<<(unsigned)((n3 / 4 + 255) / 256), 256>>>(w_o, wo_hi, wo_lo, n3);
    }

    // 1) QKV projection (pipelined split-bf16 tensor GEMM)
    {
        cudaFuncSetAttribute(bgemm3_kernel,
                             cudaFuncAttributeMaxDynamicSharedMemorySize,
                             GEMM_SMEM_BYTES);
        dim3 grid(QKV_N / 128, T_SEQ / 128);
        bgemm3_kernel<<<grid, 256, GEMM_SMEM_BYTES>>>(
            hid_hi, hid_lo, wqkv_hi, wqkv_lo, qkv_ptr, T_SEQ, QKV_N, HID);
    }

    // 2) RoPE + split to head-major bf16 hi/lo Q/K/V
    rope_split_kernel<<<dim3(T_SEQ, NH + 2 * NKV), 128>>>(positions);

    // 3) Pipelined tensor-core flash attention -> att_hi/att_lo
    {
        cudaFuncSetAttribute(attn_mma_kernel,
                             cudaFuncAttributeMaxDynamicSharedMemorySize,
                             ATT2_SMEM_BYTES);
        attn_mma_kernel<<<dim3(T_SEQ / 64, NH), 128, ATT2_SMEM_BYTES>>>();
    }

    // 4) O projection (pipelined split-bf16 tensor GEMM)
    {
        dim3 grid(HID / 128, T_SEQ / 128);
        bgemm3_kernel<<<grid, 256, GEMM_SMEM_BYTES>>>(
            att_hi, att_lo, wo_hi, wo_lo, out, T_SEQ, HID, ATT_N);
    }
}